// round 10
// baseline (speedup 1.0000x reference)
#include <cuda_runtime.h>
#include <cuda_bf16.h>
#include <math.h>
#include <stdint.h>

#define BB 4
#define SS 4096
#define DIN 1024
#define DOUT 64
#define NROWS (BB*SS)          // 16384

#define NQT (SS/128)           // 32 query tiles of 128 rows per batch
#define CHUNK 512              // keys per split-KV chunk
#define MAXCH 8
#define NPART (BB*NQT*MAXCH)   // 1024

#define KST 72                 // tile row stride (bf16 elems)
#define TILE_ELEMS (64*KST)    // 4608 per plane
#define TILE_BYTES (4*TILE_ELEMS*2)   // 36864 B per tile (4 planes)

// Scratch (no allocation allowed in kernel_launch)
__device__ float g_q[NROWS*DOUT];
__device__ float g_k[NROWS*DOUT];
__device__ float g_v[NROWS*DOUT];
__device__ float g_pacc[(size_t)NPART*128*DOUT];
__device__ float g_pl[NPART*128];
// Pre-split weights: [mat][n][k], k-contiguous, bf16 hi/lo planes
__device__ __nv_bfloat16 g_wt_hi[3*64*1024];
__device__ __nv_bfloat16 g_wt_lo[3*64*1024];
// Pre-converted KV tiles: [b*64+kt][plane][4608]
//   plane 0 = K hi [key][d], 1 = K lo, 2 = Vt hi [d][key], 3 = Vt lo
__device__ __nv_bfloat16 g_tiles[(size_t)BB*64*4*TILE_ELEMS];

// ---------------------------------------------------------------------------
// bf16 helpers: cvt2 packs first arg into LOW 16 bits (even element)
// ---------------------------------------------------------------------------
__device__ __forceinline__ uint32_t cvt2(float lo, float hi) {
    uint32_t r;
    asm("cvt.rn.bf16x2.f32 %0, %1, %2;" : "=r"(r) : "f"(hi), "f"(lo));
    return r;
}
__device__ __forceinline__ float bflo(uint32_t h) { return __uint_as_float(h << 16); }
__device__ __forceinline__ float bfhi(uint32_t h) { return __uint_as_float(h & 0xffff0000u); }

__device__ __forceinline__ uint32_t smem_u32(const void* p) {
    uint32_t a;
    asm("{ .reg .u64 t; cvta.to.shared.u64 t, %1; cvt.u32.u64 %0, t; }"
        : "=r"(a) : "l"(p));
    return a;
}

// mma.sync m16n8k16 row.col bf16 -> f32 (plain sm_80+ PTX, legal on compute_103)
// Fragment layout (validated rounds 5-9, rel_err ~6e-6):
//   A: a0=(g,2t..2t+1) a1=(g+8,2t..) a2=(g,2t+8..) a3=(g+8,2t+8..)
//   B: b0=(n=g, k=2t..2t+1) b1=(n=g, k=2t+8..2t+9)
//   C: c0,c1=(row g, cols 2t,2t+1); c2,c3=(row g+8, cols 2t,2t+1)
__device__ __forceinline__ void mma_bf16(float* d, uint32_t a0, uint32_t a1,
                                         uint32_t a2, uint32_t a3,
                                         uint32_t b0, uint32_t b1) {
    asm("mma.sync.aligned.m16n8k16.row.col.f32.bf16.bf16.f32 "
        "{%0,%1,%2,%3}, {%4,%5,%6,%7}, {%8,%9}, {%0,%1,%2,%3};"
        : "+f"(d[0]), "+f"(d[1]), "+f"(d[2]), "+f"(d[3])
        : "r"(a0), "r"(a1), "r"(a2), "r"(a3), "r"(b0), "r"(b1));
}

// ldmatrix m8n8.x4 (validated in attn round 9):
// lane l -> row (l>>4)*8+(l&7), k-half (l>>3)&1; result regs =
// {b0(even frag), b1(even frag), b0(odd frag), b1(odd frag)} of an nc pair.
__device__ __forceinline__ void ldm_x4(uint32_t& r0, uint32_t& r1,
                                       uint32_t& r2, uint32_t& r3, uint32_t addr) {
    asm volatile("ldmatrix.sync.aligned.m8n8.x4.shared.b16 {%0,%1,%2,%3}, [%4];"
                 : "=r"(r0), "=r"(r1), "=r"(r2), "=r"(r3) : "r"(addr));
}

// ---------------------------------------------------------------------------
// Kernel 0: split W into bf16 hi/lo, transposed to [mat][n][k] (k-contiguous)
// ---------------------------------------------------------------------------
__global__ __launch_bounds__(256) void prep_w_kernel(
    const float* __restrict__ Wq, const float* __restrict__ Wk,
    const float* __restrict__ Wv)
{
    int idx = blockIdx.x * 256 + threadIdx.x;     // 0 .. 196607
    int mat = idx >> 16;
    int r   = idx & 65535;
    const float* W = (mat == 0) ? Wq : (mat == 1) ? Wk : Wv;
    float w = W[r];                                // coalesced read: r = k*64+n
    int k = r >> 6;
    int n = r & 63;
    __nv_bfloat16 hi = __float2bfloat16(w);
    __nv_bfloat16 lo = __float2bfloat16(w - __bfloat162float(hi));
    int dst = (mat << 16) + n * 1024 + k;
    g_wt_hi[dst] = hi;
    g_wt_lo[dst] = lo;
}

// ---------------------------------------------------------------------------
// Kernel 1: QKV via mma.sync bf16 hi/lo; round-10: B frags via ldmatrix.x4
// ---------------------------------------------------------------------------
#define WTS 40   // bf16 elements per smem B row (80B stride, 16B-aligned,
                 // ldmatrix banks 20r mod 32 distinct for r=0..7)

__global__ __launch_bounds__(128) void qkv_mma_kernel(
    const float* __restrict__ x,
    const float* __restrict__ bq, const float* __restrict__ bk,
    const float* __restrict__ bv)
{
    __shared__ __align__(16) __nv_bfloat16 bs_hi[3 * 64 * WTS];  // 15360 B
    __shared__ __align__(16) __nv_bfloat16 bs_lo[3 * 64 * WTS];  // 15360 B

    int tid  = threadIdx.x;
    int wid  = tid >> 5;
    int lane = tid & 31;
    int g    = lane >> 2;     // 0..7
    int t    = lane & 3;      // 0..3
    int r0   = blockIdx.x * 64;
    int rA   = r0 + wid * 16 + g;          // rows rA and rA+8

    // ldmatrix per-lane byte offset within the B tile:
    // row-in-16-block = (lane>>4)*8 + (lane&7), k-half = (lane>>3)&1
    uint32_t bhi_base = smem_u32(bs_hi);
    uint32_t blo_base = smem_u32(bs_lo);
    uint32_t laneoff = (((lane >> 4) * 8 + (lane & 7)) * WTS) * 2
                       + (((lane >> 3) & 1) * 8) * 2;

    float acc[3][8][4];
#pragma unroll
    for (int m = 0; m < 3; m++)
#pragma unroll
        for (int nt = 0; nt < 8; nt++)
#pragma unroll
            for (int i = 0; i < 4; i++) acc[m][nt][i] = 0.f;

    const float* xlo = &x[(size_t)rA * DIN];
    const float* xhi = &x[(size_t)(rA + 8) * DIN];

    for (int c0 = 0; c0 < DIN; c0 += 32) {
        __syncthreads();
#pragma unroll
        for (int p = 0; p < 6; p++) {
            int i = tid + p * 128;
            int row = i >> 2;            // 0..191  (= mat*64 + n)
            int cc  = i & 3;             // 16B chunk
            int src = row * 1024 + c0 + cc * 8;
            *(uint4*)&bs_hi[row * WTS + cc * 8] = *(const uint4*)&g_wt_hi[src];
            *(uint4*)&bs_lo[row * WTS + cc * 8] = *(const uint4*)&g_wt_lo[src];
        }
        __syncthreads();

#pragma unroll
        for (int ks = 0; ks < 2; ks++) {
            int kk = c0 + ks * 16;
            float2 xa = *(const float2*)&xlo[kk + 2 * t];
            float2 xb = *(const float2*)&xlo[kk + 2 * t + 8];
            float2 xc = *(const float2*)&xhi[kk + 2 * t];
            float2 xd = *(const float2*)&xhi[kk + 2 * t + 8];
            uint32_t ah0 = cvt2(xa.x, xa.y);
            uint32_t ah1 = cvt2(xc.x, xc.y);
            uint32_t ah2 = cvt2(xb.x, xb.y);
            uint32_t ah3 = cvt2(xd.x, xd.y);
            uint32_t al0 = cvt2(xa.x - bflo(ah0), xa.y - bfhi(ah0));
            uint32_t al1 = cvt2(xc.x - bflo(ah1), xc.y - bfhi(ah1));
            uint32_t al2 = cvt2(xb.x - bflo(ah2), xb.y - bfhi(ah2));
            uint32_t al3 = cvt2(xd.x - bflo(ah3), xd.y - bfhi(ah3));

#pragma unroll
            for (int m = 0; m < 3; m++) {
#pragma unroll
                for (int np = 0; np < 4; np++) {     // nt pair 2np, 2np+1
                    uint32_t off = ((m * 64 + np * 16) * WTS + ks * 16) * 2;
                    uint32_t h0a, h1a, h0b, h1b, l0a, l1a, l0b, l1b;
                    ldm_x4(h0a, h1a, h0b, h1b, bhi_base + off + laneoff);
                    ldm_x4(l0a, l1a, l0b, l1b, blo_base + off + laneoff);
                    mma_bf16(acc[m][2*np],   ah0, ah1, ah2, ah3, h0a, h1a);
                    mma_bf16(acc[m][2*np],   ah0, ah1, ah2, ah3, l0a, l1a);
                    mma_bf16(acc[m][2*np],   al0, al1, al2, al3, h0a, h1a);
                    mma_bf16(acc[m][2*np+1], ah0, ah1, ah2, ah3, h0b, h1b);
                    mma_bf16(acc[m][2*np+1], ah0, ah1, ah2, ah3, l0b, l1b);
                    mma_bf16(acc[m][2*np+1], al0, al1, al2, al3, h0b, h1b);
                }
            }
        }
    }

#pragma unroll
    for (int m = 0; m < 3; m++) {
        float* out = (m == 0) ? g_q : (m == 1) ? g_k : g_v;
        const float* bias = (m == 0) ? bq : (m == 1) ? bk : bv;
#pragma unroll
        for (int nt = 0; nt < 8; nt++) {
            int col = nt * 8 + 2 * t;
            float b0 = bias[col], b1 = bias[col + 1];
            float2 o0 = make_float2(acc[m][nt][0] + b0, acc[m][nt][1] + b1);
            float2 o1 = make_float2(acc[m][nt][2] + b0, acc[m][nt][3] + b1);
            *(float2*)&out[(size_t)rA * DOUT + col] = o0;
            *(float2*)&out[(size_t)(rA + 8) * DOUT + col] = o1;
        }
    }
}

// ---------------------------------------------------------------------------
// Kernel 1b: pre-convert K/V into bf16 hi/lo tile images (UNCHANGED)
// ---------------------------------------------------------------------------
__global__ __launch_bounds__(256) void preconv_kernel()
{
    __shared__ float vsm[64 * 65];

    int bt  = blockIdx.x;             // b*64 + kt
    int b   = bt >> 6;
    int kt  = bt & 63;
    int tid = threadIdx.x;

    __nv_bfloat16* tk_hi = &g_tiles[((size_t)bt * 4 + 0) * TILE_ELEMS];
    __nv_bfloat16* tk_lo = &g_tiles[((size_t)bt * 4 + 1) * TILE_ELEMS];
    __nv_bfloat16* tv_hi = &g_tiles[((size_t)bt * 4 + 2) * TILE_ELEMS];
    __nv_bfloat16* tv_lo = &g_tiles[((size_t)bt * 4 + 3) * TILE_ELEMS];

#pragma unroll
    for (int p = 0; p < 4; p++) {
        int idx4 = tid + p * 256;            // 0..1023 float4s
        int key  = idx4 >> 4;
        int dq   = (idx4 & 15) * 4;
        size_t gsrc = ((size_t)b * SS + kt * 64 + key) * DOUT + dq;

        float4 kv = *(const float4*)&g_k[gsrc];
        uint32_t h0 = cvt2(kv.x, kv.y), h1 = cvt2(kv.z, kv.w);
        uint32_t l0 = cvt2(kv.x - bflo(h0), kv.y - bfhi(h0));
        uint32_t l1 = cvt2(kv.z - bflo(h1), kv.w - bfhi(h1));
        *(uint2*)&tk_hi[key * KST + dq] = make_uint2(h0, h1);
        *(uint2*)&tk_lo[key * KST + dq] = make_uint2(l0, l1);

        float4 vv = *(const float4*)&g_v[gsrc];
        vsm[key * 65 + dq + 0] = vv.x;
        vsm[key * 65 + dq + 1] = vv.y;
        vsm[key * 65 + dq + 2] = vv.z;
        vsm[key * 65 + dq + 3] = vv.w;
    }
    __syncthreads();

    {
        int d  = tid >> 2;
        int kq = (tid & 3) * 16;
        uint32_t h[8], l[8];
#pragma unroll
        for (int i = 0; i < 8; i++) {
            float f0 = vsm[(kq + 2 * i) * 65 + d];
            float f1 = vsm[(kq + 2 * i + 1) * 65 + d];
            h[i] = cvt2(f0, f1);
            l[i] = cvt2(f0 - bflo(h[i]), f1 - bfhi(h[i]));
        }
        uint4* dsth = (uint4*)&tv_hi[d * KST + kq];
        uint4* dstl = (uint4*)&tv_lo[d * KST + kq];
        dsth[0] = make_uint4(h[0], h[1], h[2], h[3]);
        dsth[1] = make_uint4(h[4], h[5], h[6], h[7]);
        dstl[0] = make_uint4(l[0], l[1], l[2], l[3]);
        dstl[1] = make_uint4(l[4], l[5], l[6], l[7]);
    }
}

// ---------------------------------------------------------------------------
// Kernel 2: flash-attention partial via mma.sync bf16 hi/lo.
// Round-10: double-buffered tile staging in dynamic smem (2 x 36864B);
// prefetch tile i+1 (cp.async group) while computing tile i.
// ---------------------------------------------------------------------------
__global__ __launch_bounds__(256, 2) void attn_mma_kernel()
{
    extern __shared__ __align__(16) char smdyn[];

    int blk = blockIdx.x;
    int b   = blk / (NQT * MAXCH);
    int rem = blk % (NQT * MAXCH);
    int qt  = rem / MAXCH;
    int ch  = rem % MAXCH;
    int nch = (qt >> 2) + 1;   // ceil((qt+1)*128 / 512)
    if (ch >= nch) return;

    int tid  = threadIdx.x;
    int w    = tid >> 5;
    int lane = tid & 31;
    int g    = lane >> 2;
    int t    = lane & 3;

    int rg  = qt * 128 + w * 16 + g;   // query rows rg and rg+8
    int rg8 = rg + 8;

    uint32_t smT_base = smem_u32(smdyn);
    uint32_t laneoff = ((((lane >> 4) * 8 + (lane & 7)) * KST
                         + ((lane >> 3) & 1) * 8) * 2);

    // Q fragments (scale folded in), hi/lo split
    const float SCALE = 0.015625f;   // 1/sqrt(4096)
    uint32_t qh[4][4], ql[4][4];
    {
        const float* q0 = &g_q[((size_t)b * SS + rg) * DOUT];
        const float* q8 = &g_q[((size_t)b * SS + rg8) * DOUT];
#pragma unroll
        for (int ks = 0; ks < 4; ks++) {
            float2 xa = *(const float2*)&q0[ks * 16 + 2 * t];
            float2 xc = *(const float2*)&q8[ks * 16 + 2 * t];
            float2 xb = *(const float2*)&q0[ks * 16 + 2 * t + 8];
            float2 xd = *(const float2*)&q8[ks * 16 + 2 * t + 8];
            xa.x *= SCALE; xa.y *= SCALE; xb.x *= SCALE; xb.y *= SCALE;
            xc.x *= SCALE; xc.y *= SCALE; xd.x *= SCALE; xd.y *= SCALE;
            qh[ks][0] = cvt2(xa.x, xa.y);
            qh[ks][1] = cvt2(xc.x, xc.y);
            qh[ks][2] = cvt2(xb.x, xb.y);
            qh[ks][3] = cvt2(xd.x, xd.y);
            ql[ks][0] = cvt2(xa.x - bflo(qh[ks][0]), xa.y - bfhi(qh[ks][0]));
            ql[ks][1] = cvt2(xc.x - bflo(qh[ks][1]), xc.y - bfhi(qh[ks][1]));
            ql[ks][2] = cvt2(xb.x - bflo(qh[ks][2]), xb.y - bfhi(qh[ks][2]));
            ql[ks][3] = cvt2(xd.x - bflo(qh[ks][3]), xd.y - bfhi(qh[ks][3]));
        }
    }

    float o[8][4];
#pragma unroll
    for (int nd = 0; nd < 8; nd++)
#pragma unroll
        for (int i = 0; i < 4; i++) o[nd][i] = 0.f;
    float lg = 0.f, lg8 = 0.f;

    int k0 = ch * CHUNK;
    int k1 = min(k0 + CHUNK, (qt + 1) * 128);

    // ---- prologue: stage first tile into buffer 0
    {
        const char* src =
            (const char*)&g_tiles[((size_t)(b * 64 + (k0 >> 6)) * 4) * TILE_ELEMS];
#pragma unroll
        for (int p = 0; p < 9; p++) {
            int i = tid + p * 256;
            asm volatile("cp.async.cg.shared.global [%0], [%1], 16;"
                         :: "r"(smT_base + i * 16), "l"(src + (size_t)i * 16)
                         : "memory");
        }
        asm volatile("cp.async.commit_group;" ::: "memory");
    }

    int ib = 0;
    for (int kt = k0; kt < k1; kt += 64, ib ^= 1) {
        int ktn = kt + 64;
        // ---- prefetch next tile into the other buffer
        if (ktn < k1) {
            uint32_t nb = smT_base + (ib ^ 1) * TILE_BYTES;
            const char* src =
                (const char*)&g_tiles[((size_t)(b * 64 + (ktn >> 6)) * 4) * TILE_ELEMS];
#pragma unroll
            for (int p = 0; p < 9; p++) {
                int i = tid + p * 256;
                asm volatile("cp.async.cg.shared.global [%0], [%1], 16;"
                             :: "r"(nb + i * 16), "l"(src + (size_t)i * 16)
                             : "memory");
            }
            asm volatile("cp.async.commit_group;" ::: "memory");
            asm volatile("cp.async.wait_group 1;" ::: "memory");
        } else {
            asm volatile("cp.async.wait_group 0;" ::: "memory");
        }
        __syncthreads();

        uint32_t bufb  = smT_base + ib * TILE_BYTES;
        uint32_t aK_hi = bufb + 0 * TILE_ELEMS * 2 + laneoff;
        uint32_t aK_lo = bufb + 1 * TILE_ELEMS * 2 + laneoff;
        uint32_t aV_hi = bufb + 2 * TILE_ELEMS * 2 + laneoff;
        uint32_t aV_lo = bufb + 3 * TILE_ELEMS * 2 + laneoff;

        // ---- QK^T: 3-pass hi/lo, fp32 C; B frags via ldmatrix.x4
        float c[8][4];
#pragma unroll
        for (int nc = 0; nc < 8; nc++)
#pragma unroll
            for (int i = 0; i < 4; i++) c[nc][i] = 0.f;

#pragma unroll
        for (int ks = 0; ks < 4; ks++) {
#pragma unroll
            for (int np = 0; np < 4; np++) {     // nc pair 2np, 2np+1
                uint32_t off = (np * 16 * KST + ks * 16) * 2;
                uint32_t h0a, h1a, h0b, h1b, l0a, l1a, l0b, l1b;
                ldm_x4(h0a, h1a, h0b, h1b, aK_hi + off);
                ldm_x4(l0a, l1a, l0b, l1b, aK_lo + off);
                mma_bf16(c[2*np],   qh[ks][0], qh[ks][1], qh[ks][2], qh[ks][3], h0a, h1a);
                mma_bf16(c[2*np],   qh[ks][0], qh[ks][1], qh[ks][2], qh[ks][3], l0a, l1a);
                mma_bf16(c[2*np],   ql[ks][0], ql[ks][1], ql[ks][2], ql[ks][3], h0a, h1a);
                mma_bf16(c[2*np+1], qh[ks][0], qh[ks][1], qh[ks][2], qh[ks][3], h0b, h1b);
                mma_bf16(c[2*np+1], qh[ks][0], qh[ks][1], qh[ks][2], qh[ks][3], l0b, l1b);
                mma_bf16(c[2*np+1], ql[ks][0], ql[ks][1], ql[ks][2], ql[ks][3], h0b, h1b);
            }
        }

        // ---- masked exp; pack P into PV A-fragments (hi/lo)
        uint32_t pah[4][4], pal[4][4];
#pragma unroll
        for (int nc = 0; nc < 8; nc++) {
            int col0 = kt + nc * 8 + 2 * t;
            int col1 = col0 + 1;
            float e0 = (col0 <= rg)  ? __expf(c[nc][0]) : 0.f;
            float e1 = (col1 <= rg)  ? __expf(c[nc][1]) : 0.f;
            float e2 = (col0 <= rg8) ? __expf(c[nc][2]) : 0.f;
            float e3 = (col1 <= rg8) ? __expf(c[nc][3]) : 0.f;
            lg  += e0 + e1;
            lg8 += e2 + e3;
            uint32_t h01 = cvt2(e0, e1), h23 = cvt2(e2, e3);
            uint32_t l01 = cvt2(e0 - bflo(h01), e1 - bfhi(h01));
            uint32_t l23 = cvt2(e2 - bflo(h23), e3 - bfhi(h23));
            int j = nc >> 1;
            if ((nc & 1) == 0) {
                pah[j][0] = h01; pah[j][1] = h23;
                pal[j][0] = l01; pal[j][1] = l23;
            } else {
                pah[j][2] = h01; pah[j][3] = h23;
                pal[j][2] = l01; pal[j][3] = l23;
            }
        }

        // ---- PV: 3-pass hi/lo, B frags via ldmatrix.x4
#pragma unroll
        for (int j = 0; j < 4; j++) {
#pragma unroll
            for (int np = 0; np < 4; np++) {     // nd pair 2np, 2np+1
                uint32_t off = (np * 16 * KST + j * 16) * 2;
                uint32_t h0a, h1a, h0b, h1b, l0a, l1a, l0b, l1b;
                ldm_x4(h0a, h1a, h0b, h1b, aV_hi + off);
                ldm_x4(l0a, l1a, l0b, l1b, aV_lo + off);
                mma_bf16(o[2*np],   pah[j][0], pah[j][1], pah[j][2], pah[j][3], h0a, h1a);
                mma_bf16(o[2*np],   pah[j][0], pah[j][1], pah[j][2], pah[j][3], l0a, l1a);
                mma_bf16(o[2*np],   pal[j][0], pal[j][1], pal[j][2], pal[j][3], h0a, h1a);
                mma_bf16(o[2*np+1], pah[j][0], pah[j][1], pah[j][2], pah[j][3], h0b, h1b);
                mma_bf16(o[2*np+1], pah[j][0], pah[j][1], pah[j][2], pah[j][3], l0b, l1b);
                mma_bf16(o[2*np+1], pal[j][0], pal[j][1], pal[j][2], pal[j][3], h0b, h1b);
            }
        }
        __syncthreads();   // all reads of buf ib done before next prefetch overwrites it
    }

    // ---- l reduce across the t-quad (lanes g*4 + t)
    lg  += __shfl_xor_sync(0xffffffffu, lg, 1);
    lg  += __shfl_xor_sync(0xffffffffu, lg, 2);
    lg8 += __shfl_xor_sync(0xffffffffu, lg8, 1);
    lg8 += __shfl_xor_sync(0xffffffffu, lg8, 2);

    int pidx = (b * NQT + qt) * MAXCH + ch;
    int rl = w * 16 + g;
    if (t == 0) {
        g_pl[pidx * 128 + rl]     = lg;
        g_pl[pidx * 128 + rl + 8] = lg8;
    }
    float* pa0 = &g_pacc[((size_t)pidx * 128 + rl) * DOUT];
    float* pa8 = &g_pacc[((size_t)pidx * 128 + rl + 8) * DOUT];
#pragma unroll
    for (int nd = 0; nd < 8; nd++) {
        *(float2*)&pa0[nd * 8 + 2 * t] = make_float2(o[nd][0], o[nd][1]);
        *(float2*)&pa8[nd * 8 + 2 * t] = make_float2(o[nd][2], o[nd][3]);
    }
}

// ---------------------------------------------------------------------------
// Kernel 3: combine split-KV partials. grid = B*S blocks, 64 threads (=d).
// ---------------------------------------------------------------------------
__global__ __launch_bounds__(64) void combine_kernel(float* __restrict__ out)
{
    int blk = blockIdx.x;
    int b   = blk / SS;
    int row = blk % SS;
    int qt  = row >> 7;
    int r   = row & 127;
    int nch = (qt >> 2) + 1;
    int d   = threadIdx.x;
    int pbase = (b * NQT + qt) * MAXCH;

    float L = 0.f, o = 0.f;
    for (int c = 0; c < nch; c++) {
        L += g_pl[(pbase + c) * 128 + r];
        o += g_pacc[((size_t)(pbase + c) * 128 + r) * DOUT + d];
    }
    out[((size_t)b * SS + row) * DOUT + d] = o / L;
}

// ---------------------------------------------------------------------------
extern "C" void kernel_launch(void* const* d_in, const int* in_sizes, int n_in,
                              void* d_out, int out_size)
{
    const float* x  = (const float*)d_in[0];
    const float* Wq = (const float*)d_in[1];
    const float* bq = (const float*)d_in[2];
    const float* Wk = (const float*)d_in[3];
    const float* bk = (const float*)d_in[4];
    const float* Wv = (const float*)d_in[5];
    const float* bv = (const float*)d_in[6];
    float* out = (float*)d_out;

    // Attribute set is idempotent and not stream-ordered (graph-capture safe).
    cudaFuncSetAttribute(attn_mma_kernel,
                         cudaFuncAttributeMaxDynamicSharedMemorySize,
                         2 * TILE_BYTES);

    prep_w_kernel<<<768, 256>>>(Wq, Wk, Wv);
    qkv_mma_kernel<<<NROWS / 64, 128>>>(x, bq, bk, bv);
    preconv_kernel<<<BB * 64, 256>>>();
    attn_mma_kernel<<<NPART, 256, 2 * TILE_BYTES>>>();
    combine_kernel<<<BB * SS, 64>>>(out);
}

// round 11
// speedup vs baseline: 1.1208x; 1.1208x over previous
#include <cuda_runtime.h>
#include <cuda_bf16.h>
#include <cuda_fp16.h>
#include <math.h>
#include <stdint.h>

#define BB 4
#define SS 4096
#define DIN 1024
#define DOUT 64
#define NROWS (BB*SS)          // 16384

#define NQT (SS/128)           // 32 query tiles of 128 rows per batch
#define CHUNK 512              // keys per split-KV chunk
#define MAXCH 8
#define NPART (BB*NQT*MAXCH)   // 1024

#define KST 72                 // tile row stride (f16 elems)
#define TILE_ELEMS (64*KST)    // 4608 per plane
#define TILE_BYTES (4*TILE_ELEMS*2)   // 36864 B per tile (4 planes)

// Scratch (no allocation allowed in kernel_launch)
__device__ float g_q[NROWS*DOUT];
__device__ float g_k[NROWS*DOUT];
__device__ float g_v[NROWS*DOUT];
__device__ float g_pacc[(size_t)NPART*128*DOUT];
__device__ float g_pl[NPART*128];
// Pre-split weights: [mat][n][k], k-contiguous, bf16 hi/lo planes (QKV path)
__device__ __nv_bfloat16 g_wt_hi[3*64*1024];
__device__ __nv_bfloat16 g_wt_lo[3*64*1024];
// Pre-converted KV tiles (fp16 hi/lo): [b*64+kt][plane][4608]
//   plane 0 = K hi [key][d], 1 = K lo, 2 = Vt hi [d][key], 3 = Vt lo
__device__ __half g_tiles[(size_t)BB*64*4*TILE_ELEMS];

// ---------------------------------------------------------------------------
// bf16 helpers (QKV path): cvt2 packs first arg into LOW 16 bits
// ---------------------------------------------------------------------------
__device__ __forceinline__ uint32_t cvt2(float lo, float hi) {
    uint32_t r;
    asm("cvt.rn.bf16x2.f32 %0, %1, %2;" : "=r"(r) : "f"(hi), "f"(lo));
    return r;
}
__device__ __forceinline__ float bflo(uint32_t h) { return __uint_as_float(h << 16); }
__device__ __forceinline__ float bfhi(uint32_t h) { return __uint_as_float(h & 0xffff0000u); }

// fp16 helpers (attention path): same packing convention (first arg -> low half)
__device__ __forceinline__ uint32_t cvtf2(float lo, float hi) {
    uint32_t r;
    asm("cvt.rn.f16x2.f32 %0, %1, %2;" : "=r"(r) : "f"(hi), "f"(lo));
    return r;
}
__device__ __forceinline__ float2 f16x2_f32(uint32_t h) {
    float lo, hi;
    asm("{ .reg .b16 a, b; mov.b32 {a, b}, %2; "
        "cvt.f32.f16 %0, a; cvt.f32.f16 %1, b; }"
        : "=f"(lo), "=f"(hi) : "r"(h));
    return make_float2(lo, hi);
}

__device__ __forceinline__ uint32_t smem_u32(const void* p) {
    uint32_t a;
    asm("{ .reg .u64 t; cvta.to.shared.u64 t, %1; cvt.u32.u64 %0, t; }"
        : "=r"(a) : "l"(p));
    return a;
}

// mma.sync m16n8k16 row.col -> f32 (sm_80+ PTX; fragment layout validated r5-10)
__device__ __forceinline__ void mma_bf16(float* d, uint32_t a0, uint32_t a1,
                                         uint32_t a2, uint32_t a3,
                                         uint32_t b0, uint32_t b1) {
    asm("mma.sync.aligned.m16n8k16.row.col.f32.bf16.bf16.f32 "
        "{%0,%1,%2,%3}, {%4,%5,%6,%7}, {%8,%9}, {%0,%1,%2,%3};"
        : "+f"(d[0]), "+f"(d[1]), "+f"(d[2]), "+f"(d[3])
        : "r"(a0), "r"(a1), "r"(a2), "r"(a3), "r"(b0), "r"(b1));
}
__device__ __forceinline__ void mma_f16(float* d, uint32_t a0, uint32_t a1,
                                        uint32_t a2, uint32_t a3,
                                        uint32_t b0, uint32_t b1) {
    asm("mma.sync.aligned.m16n8k16.row.col.f32.f16.f16.f32 "
        "{%0,%1,%2,%3}, {%4,%5,%6,%7}, {%8,%9}, {%0,%1,%2,%3};"
        : "+f"(d[0]), "+f"(d[1]), "+f"(d[2]), "+f"(d[3])
        : "r"(a0), "r"(a1), "r"(a2), "r"(a3), "r"(b0), "r"(b1));
}

// ldmatrix m8n8.x4 (validated r9/r10)
__device__ __forceinline__ void ldm_x4(uint32_t& r0, uint32_t& r1,
                                       uint32_t& r2, uint32_t& r3, uint32_t addr) {
    asm volatile("ldmatrix.sync.aligned.m8n8.x4.shared.b16 {%0,%1,%2,%3}, [%4];"
                 : "=r"(r0), "=r"(r1), "=r"(r2), "=r"(r3) : "r"(addr));
}

// ---------------------------------------------------------------------------
// Kernel 0: split W into bf16 hi/lo, transposed to [mat][n][k] (UNCHANGED)
// ---------------------------------------------------------------------------
__global__ __launch_bounds__(256) void prep_w_kernel(
    const float* __restrict__ Wq, const float* __restrict__ Wk,
    const float* __restrict__ Wv)
{
    int idx = blockIdx.x * 256 + threadIdx.x;     // 0 .. 196607
    int mat = idx >> 16;
    int r   = idx & 65535;
    const float* W = (mat == 0) ? Wq : (mat == 1) ? Wk : Wv;
    float w = W[r];                                // coalesced read: r = k*64+n
    int k = r >> 6;
    int n = r & 63;
    __nv_bfloat16 hi = __float2bfloat16(w);
    __nv_bfloat16 lo = __float2bfloat16(w - __bfloat162float(hi));
    int dst = (mat << 16) + n * 1024 + k;
    g_wt_hi[dst] = hi;
    g_wt_lo[dst] = lo;
}

// ---------------------------------------------------------------------------
// Kernel 1: QKV via mma.sync bf16 hi/lo + ldmatrix (UNCHANGED from r10)
// ---------------------------------------------------------------------------
#define WTS 40   // bf16 elements per smem B row (80B stride)

__global__ __launch_bounds__(128) void qkv_mma_kernel(
    const float* __restrict__ x,
    const float* __restrict__ bq, const float* __restrict__ bk,
    const float* __restrict__ bv)
{
    __shared__ __align__(16) __nv_bfloat16 bs_hi[3 * 64 * WTS];  // 15360 B
    __shared__ __align__(16) __nv_bfloat16 bs_lo[3 * 64 * WTS];  // 15360 B

    int tid  = threadIdx.x;
    int wid  = tid >> 5;
    int lane = tid & 31;
    int g    = lane >> 2;     // 0..7
    int t    = lane & 3;      // 0..3
    int r0   = blockIdx.x * 64;
    int rA   = r0 + wid * 16 + g;          // rows rA and rA+8

    uint32_t bhi_base = smem_u32(bs_hi);
    uint32_t blo_base = smem_u32(bs_lo);
    uint32_t laneoff = (((lane >> 4) * 8 + (lane & 7)) * WTS) * 2
                       + (((lane >> 3) & 1) * 8) * 2;

    float acc[3][8][4];
#pragma unroll
    for (int m = 0; m < 3; m++)
#pragma unroll
        for (int nt = 0; nt < 8; nt++)
#pragma unroll
            for (int i = 0; i < 4; i++) acc[m][nt][i] = 0.f;

    const float* xlo = &x[(size_t)rA * DIN];
    const float* xhi = &x[(size_t)(rA + 8) * DIN];

    for (int c0 = 0; c0 < DIN; c0 += 32) {
        __syncthreads();
#pragma unroll
        for (int p = 0; p < 6; p++) {
            int i = tid + p * 128;
            int row = i >> 2;            // 0..191  (= mat*64 + n)
            int cc  = i & 3;             // 16B chunk
            int src = row * 1024 + c0 + cc * 8;
            *(uint4*)&bs_hi[row * WTS + cc * 8] = *(const uint4*)&g_wt_hi[src];
            *(uint4*)&bs_lo[row * WTS + cc * 8] = *(const uint4*)&g_wt_lo[src];
        }
        __syncthreads();

#pragma unroll
        for (int ks = 0; ks < 2; ks++) {
            int kk = c0 + ks * 16;
            float2 xa = *(const float2*)&xlo[kk + 2 * t];
            float2 xb = *(const float2*)&xlo[kk + 2 * t + 8];
            float2 xc = *(const float2*)&xhi[kk + 2 * t];
            float2 xd = *(const float2*)&xhi[kk + 2 * t + 8];
            uint32_t ah0 = cvt2(xa.x, xa.y);
            uint32_t ah1 = cvt2(xc.x, xc.y);
            uint32_t ah2 = cvt2(xb.x, xb.y);
            uint32_t ah3 = cvt2(xd.x, xd.y);
            uint32_t al0 = cvt2(xa.x - bflo(ah0), xa.y - bfhi(ah0));
            uint32_t al1 = cvt2(xc.x - bflo(ah1), xc.y - bfhi(ah1));
            uint32_t al2 = cvt2(xb.x - bflo(ah2), xb.y - bfhi(ah2));
            uint32_t al3 = cvt2(xd.x - bflo(ah3), xd.y - bfhi(ah3));

#pragma unroll
            for (int m = 0; m < 3; m++) {
#pragma unroll
                for (int np = 0; np < 4; np++) {     // nt pair 2np, 2np+1
                    uint32_t off = ((m * 64 + np * 16) * WTS + ks * 16) * 2;
                    uint32_t h0a, h1a, h0b, h1b, l0a, l1a, l0b, l1b;
                    ldm_x4(h0a, h1a, h0b, h1b, bhi_base + off + laneoff);
                    ldm_x4(l0a, l1a, l0b, l1b, blo_base + off + laneoff);
                    mma_bf16(acc[m][2*np],   ah0, ah1, ah2, ah3, h0a, h1a);
                    mma_bf16(acc[m][2*np],   ah0, ah1, ah2, ah3, l0a, l1a);
                    mma_bf16(acc[m][2*np],   al0, al1, al2, al3, h0a, h1a);
                    mma_bf16(acc[m][2*np+1], ah0, ah1, ah2, ah3, h0b, h1b);
                    mma_bf16(acc[m][2*np+1], ah0, ah1, ah2, ah3, l0b, l1b);
                    mma_bf16(acc[m][2*np+1], al0, al1, al2, al3, h0b, h1b);
                }
            }
        }
    }

#pragma unroll
    for (int m = 0; m < 3; m++) {
        float* out = (m == 0) ? g_q : (m == 1) ? g_k : g_v;
        const float* bias = (m == 0) ? bq : (m == 1) ? bk : bv;
#pragma unroll
        for (int nt = 0; nt < 8; nt++) {
            int col = nt * 8 + 2 * t;
            float b0 = bias[col], b1 = bias[col + 1];
            float2 o0 = make_float2(acc[m][nt][0] + b0, acc[m][nt][1] + b1);
            float2 o1 = make_float2(acc[m][nt][2] + b0, acc[m][nt][3] + b1);
            *(float2*)&out[(size_t)rA * DOUT + col] = o0;
            *(float2*)&out[(size_t)(rA + 8) * DOUT + col] = o1;
        }
    }
}

// ---------------------------------------------------------------------------
// Kernel 1b: pre-convert K/V into fp16 hi/lo tile images (once per tile).
// ---------------------------------------------------------------------------
__global__ __launch_bounds__(256) void preconv_kernel()
{
    __shared__ float vsm[64 * 65];

    int bt  = blockIdx.x;             // b*64 + kt
    int b   = bt >> 6;
    int kt  = bt & 63;
    int tid = threadIdx.x;

    __half* tk_hi = &g_tiles[((size_t)bt * 4 + 0) * TILE_ELEMS];
    __half* tk_lo = &g_tiles[((size_t)bt * 4 + 1) * TILE_ELEMS];
    __half* tv_hi = &g_tiles[((size_t)bt * 4 + 2) * TILE_ELEMS];
    __half* tv_lo = &g_tiles[((size_t)bt * 4 + 3) * TILE_ELEMS];

#pragma unroll
    for (int p = 0; p < 4; p++) {
        int idx4 = tid + p * 256;            // 0..1023 float4s
        int key  = idx4 >> 4;
        int dq   = (idx4 & 15) * 4;
        size_t gsrc = ((size_t)b * SS + kt * 64 + key) * DOUT + dq;

        float4 kv = *(const float4*)&g_k[gsrc];
        uint32_t h0 = cvtf2(kv.x, kv.y), h1 = cvtf2(kv.z, kv.w);
        float2 hb0 = f16x2_f32(h0), hb1 = f16x2_f32(h1);
        uint32_t l0 = cvtf2(kv.x - hb0.x, kv.y - hb0.y);
        uint32_t l1 = cvtf2(kv.z - hb1.x, kv.w - hb1.y);
        *(uint2*)&tk_hi[key * KST + dq] = make_uint2(h0, h1);
        *(uint2*)&tk_lo[key * KST + dq] = make_uint2(l0, l1);

        float4 vv = *(const float4*)&g_v[gsrc];
        vsm[key * 65 + dq + 0] = vv.x;
        vsm[key * 65 + dq + 1] = vv.y;
        vsm[key * 65 + dq + 2] = vv.z;
        vsm[key * 65 + dq + 3] = vv.w;
    }
    __syncthreads();

    {
        int d  = tid >> 2;
        int kq = (tid & 3) * 16;
        uint32_t h[8], l[8];
#pragma unroll
        for (int i = 0; i < 8; i++) {
            float f0 = vsm[(kq + 2 * i) * 65 + d];
            float f1 = vsm[(kq + 2 * i + 1) * 65 + d];
            h[i] = cvtf2(f0, f1);
            float2 hb = f16x2_f32(h[i]);
            l[i] = cvtf2(f0 - hb.x, f1 - hb.y);
        }
        uint4* dsth = (uint4*)&tv_hi[d * KST + kq];
        uint4* dstl = (uint4*)&tv_lo[d * KST + kq];
        dsth[0] = make_uint4(h[0], h[1], h[2], h[3]);
        dsth[1] = make_uint4(h[4], h[5], h[6], h[7]);
        dstl[0] = make_uint4(l[0], l[1], l[2], l[3]);
        dstl[1] = make_uint4(l[4], l[5], l[6], l[7]);
    }
}

// ---------------------------------------------------------------------------
// Kernel 2: flash-attention partial via mma.sync fp16, 2-pass hi/lo.
// QK = qh*(kh + kl)  (drops ql*k ~1e-5 on scores);
// PV = ph*(vh + vl)  (drops pl*v ~2.4e-4 rel on output).
// Double-buffered staging (r10), ldmatrix B-frags (r9).
// ---------------------------------------------------------------------------
__global__ __launch_bounds__(256, 2) void attn_mma_kernel()
{
    extern __shared__ __align__(16) char smdyn[];

    int blk = blockIdx.x;
    int b   = blk / (NQT * MAXCH);
    int rem = blk % (NQT * MAXCH);
    int qt  = rem / MAXCH;
    int ch  = rem % MAXCH;
    int nch = (qt >> 2) + 1;   // ceil((qt+1)*128 / 512)
    if (ch >= nch) return;

    int tid  = threadIdx.x;
    int w    = tid >> 5;
    int lane = tid & 31;
    int g    = lane >> 2;
    int t    = lane & 3;

    int rg  = qt * 128 + w * 16 + g;   // query rows rg and rg+8
    int rg8 = rg + 8;

    uint32_t smT_base = smem_u32(smdyn);
    uint32_t laneoff = ((((lane >> 4) * 8 + (lane & 7)) * KST
                         + ((lane >> 3) & 1) * 8) * 2);

    // Q fragments (scale folded in), fp16 hi only
    const float SCALE = 0.015625f;   // 1/sqrt(4096)
    uint32_t qh[4][4];
    {
        const float* q0 = &g_q[((size_t)b * SS + rg) * DOUT];
        const float* q8 = &g_q[((size_t)b * SS + rg8) * DOUT];
#pragma unroll
        for (int ks = 0; ks < 4; ks++) {
            float2 xa = *(const float2*)&q0[ks * 16 + 2 * t];
            float2 xc = *(const float2*)&q8[ks * 16 + 2 * t];
            float2 xb = *(const float2*)&q0[ks * 16 + 2 * t + 8];
            float2 xd = *(const float2*)&q8[ks * 16 + 2 * t + 8];
            qh[ks][0] = cvtf2(xa.x * SCALE, xa.y * SCALE);
            qh[ks][1] = cvtf2(xc.x * SCALE, xc.y * SCALE);
            qh[ks][2] = cvtf2(xb.x * SCALE, xb.y * SCALE);
            qh[ks][3] = cvtf2(xd.x * SCALE, xd.y * SCALE);
        }
    }

    float o[8][4];
#pragma unroll
    for (int nd = 0; nd < 8; nd++)
#pragma unroll
        for (int i = 0; i < 4; i++) o[nd][i] = 0.f;
    float lg = 0.f, lg8 = 0.f;

    int k0 = ch * CHUNK;
    int k1 = min(k0 + CHUNK, (qt + 1) * 128);

    // ---- prologue: stage first tile into buffer 0
    {
        const char* src =
            (const char*)&g_tiles[((size_t)(b * 64 + (k0 >> 6)) * 4) * TILE_ELEMS];
#pragma unroll
        for (int p = 0; p < 9; p++) {
            int i = tid + p * 256;
            asm volatile("cp.async.cg.shared.global [%0], [%1], 16;"
                         :: "r"(smT_base + i * 16), "l"(src + (size_t)i * 16)
                         : "memory");
        }
        asm volatile("cp.async.commit_group;" ::: "memory");
    }

    int ib = 0;
    for (int kt = k0; kt < k1; kt += 64, ib ^= 1) {
        int ktn = kt + 64;
        if (ktn < k1) {
            uint32_t nb = smT_base + (ib ^ 1) * TILE_BYTES;
            const char* src =
                (const char*)&g_tiles[((size_t)(b * 64 + (ktn >> 6)) * 4) * TILE_ELEMS];
#pragma unroll
            for (int p = 0; p < 9; p++) {
                int i = tid + p * 256;
                asm volatile("cp.async.cg.shared.global [%0], [%1], 16;"
                             :: "r"(nb + i * 16), "l"(src + (size_t)i * 16)
                             : "memory");
            }
            asm volatile("cp.async.commit_group;" ::: "memory");
            asm volatile("cp.async.wait_group 1;" ::: "memory");
        } else {
            asm volatile("cp.async.wait_group 0;" ::: "memory");
        }
        __syncthreads();

        uint32_t bufb  = smT_base + ib * TILE_BYTES;
        uint32_t aK_hi = bufb + 0 * TILE_ELEMS * 2 + laneoff;
        uint32_t aK_lo = bufb + 1 * TILE_ELEMS * 2 + laneoff;
        uint32_t aV_hi = bufb + 2 * TILE_ELEMS * 2 + laneoff;
        uint32_t aV_lo = bufb + 3 * TILE_ELEMS * 2 + laneoff;

        // ---- QK^T: 2-pass fp16 (qh*kh + qh*kl), fp32 C
        float c[8][4];
#pragma unroll
        for (int nc = 0; nc < 8; nc++)
#pragma unroll
            for (int i = 0; i < 4; i++) c[nc][i] = 0.f;

#pragma unroll
        for (int ks = 0; ks < 4; ks++) {
#pragma unroll
            for (int np = 0; np < 4; np++) {     // nc pair 2np, 2np+1
                uint32_t off = (np * 16 * KST + ks * 16) * 2;
                uint32_t h0a, h1a, h0b, h1b, l0a, l1a, l0b, l1b;
                ldm_x4(h0a, h1a, h0b, h1b, aK_hi + off);
                ldm_x4(l0a, l1a, l0b, l1b, aK_lo + off);
                mma_f16(c[2*np],   qh[ks][0], qh[ks][1], qh[ks][2], qh[ks][3], h0a, h1a);
                mma_f16(c[2*np],   qh[ks][0], qh[ks][1], qh[ks][2], qh[ks][3], l0a, l1a);
                mma_f16(c[2*np+1], qh[ks][0], qh[ks][1], qh[ks][2], qh[ks][3], h0b, h1b);
                mma_f16(c[2*np+1], qh[ks][0], qh[ks][1], qh[ks][2], qh[ks][3], l0b, l1b);
            }
        }

        // ---- masked exp; pack P (fp16 hi only) into PV A-fragments
        uint32_t pah[4][4];
#pragma unroll
        for (int nc = 0; nc < 8; nc++) {
            int col0 = kt + nc * 8 + 2 * t;
            int col1 = col0 + 1;
            float e0 = (col0 <= rg)  ? __expf(c[nc][0]) : 0.f;
            float e1 = (col1 <= rg)  ? __expf(c[nc][1]) : 0.f;
            float e2 = (col0 <= rg8) ? __expf(c[nc][2]) : 0.f;
            float e3 = (col1 <= rg8) ? __expf(c[nc][3]) : 0.f;
            lg  += e0 + e1;
            lg8 += e2 + e3;
            uint32_t h01 = cvtf2(e0, e1), h23 = cvtf2(e2, e3);
            int j = nc >> 1;
            if ((nc & 1) == 0) { pah[j][0] = h01; pah[j][1] = h23; }
            else               { pah[j][2] = h01; pah[j][3] = h23; }
        }

        // ---- PV: 2-pass fp16 (ph*vh + ph*vl)
#pragma unroll
        for (int j = 0; j < 4; j++) {
#pragma unroll
            for (int np = 0; np < 4; np++) {     // nd pair 2np, 2np+1
                uint32_t off = (np * 16 * KST + j * 16) * 2;
                uint32_t h0a, h1a, h0b, h1b, l0a, l1a, l0b, l1b;
                ldm_x4(h0a, h1a, h0b, h1b, aV_hi + off);
                ldm_x4(l0a, l1a, l0b, l1b, aV_lo + off);
                mma_f16(o[2*np],   pah[j][0], pah[j][1], pah[j][2], pah[j][3], h0a, h1a);
                mma_f16(o[2*np],   pah[j][0], pah[j][1], pah[j][2], pah[j][3], l0a, l1a);
                mma_f16(o[2*np+1], pah[j][0], pah[j][1], pah[j][2], pah[j][3], h0b, h1b);
                mma_f16(o[2*np+1], pah[j][0], pah[j][1], pah[j][2], pah[j][3], l0b, l1b);
            }
        }
        __syncthreads();   // all reads of buf ib done before next prefetch overwrites it
    }

    // ---- l reduce across the t-quad (lanes g*4 + t)
    lg  += __shfl_xor_sync(0xffffffffu, lg, 1);
    lg  += __shfl_xor_sync(0xffffffffu, lg, 2);
    lg8 += __shfl_xor_sync(0xffffffffu, lg8, 1);
    lg8 += __shfl_xor_sync(0xffffffffu, lg8, 2);

    int pidx = (b * NQT + qt) * MAXCH + ch;
    int rl = w * 16 + g;
    if (t == 0) {
        g_pl[pidx * 128 + rl]     = lg;
        g_pl[pidx * 128 + rl + 8] = lg8;
    }
    float* pa0 = &g_pacc[((size_t)pidx * 128 + rl) * DOUT];
    float* pa8 = &g_pacc[((size_t)pidx * 128 + rl + 8) * DOUT];
#pragma unroll
    for (int nd = 0; nd < 8; nd++) {
        *(float2*)&pa0[nd * 8 + 2 * t] = make_float2(o[nd][0], o[nd][1]);
        *(float2*)&pa8[nd * 8 + 2 * t] = make_float2(o[nd][2], o[nd][3]);
    }
}

// ---------------------------------------------------------------------------
// Kernel 3: combine split-KV partials. grid = B*S blocks, 64 threads (=d).
// ---------------------------------------------------------------------------
__global__ __launch_bounds__(64) void combine_kernel(float* __restrict__ out)
{
    int blk = blockIdx.x;
    int b   = blk / SS;
    int row = blk % SS;
    int qt  = row >> 7;
    int r   = row & 127;
    int nch = (qt >> 2) + 1;
    int d   = threadIdx.x;
    int pbase = (b * NQT + qt) * MAXCH;

    float L = 0.f, o = 0.f;
    for (int c = 0; c < nch; c++) {
        L += g_pl[(pbase + c) * 128 + r];
        o += g_pacc[((size_t)(pbase + c) * 128 + r) * DOUT + d];
    }
    out[((size_t)b * SS + row) * DOUT + d] = o / L;
}

// ---------------------------------------------------------------------------
extern "C" void kernel_launch(void* const* d_in, const int* in_sizes, int n_in,
                              void* d_out, int out_size)
{
    const float* x  = (const float*)d_in[0];
    const float* Wq = (const float*)d_in[1];
    const float* bq = (const float*)d_in[2];
    const float* Wk = (const float*)d_in[3];
    const float* bk = (const float*)d_in[4];
    const float* Wv = (const float*)d_in[5];
    const float* bv = (const float*)d_in[6];
    float* out = (float*)d_out;

    cudaFuncSetAttribute(attn_mma_kernel,
                         cudaFuncAttributeMaxDynamicSharedMemorySize,
                         2 * TILE_BYTES);

    prep_w_kernel<<<768, 256>>>(Wq, Wk, Wv);
    qkv_mma_kernel<<<NROWS / 64, 128>>>(x, bq, bk, bv);
    preconv_kernel<<<BB * 64, 256>>>();
    attn_mma_kernel<<<NPART, 256, 2 * TILE_BYTES>>>();
    combine_kernel<<<BB * SS, 64>>>(out);
}

// round 12
// speedup vs baseline: 1.1473x; 1.0236x over previous
#include <cuda_runtime.h>
#include <cuda_bf16.h>
#include <cuda_fp16.h>
#include <math.h>
#include <stdint.h>

#define BB 4
#define SS 4096
#define DIN 1024
#define DOUT 64
#define NROWS (BB*SS)          // 16384

#define NQT (SS/128)           // 32 query tiles of 128 rows per batch
#define CHUNK 512              // keys per split-KV chunk
#define MAXCH 8
#define NPART (BB*NQT*MAXCH)   // 1024

#define KST 72                 // tile row stride (f16 elems)
#define TILE_ELEMS (64*KST)    // 4608 per plane
#define TILE_BYTES (4*TILE_ELEMS*2)   // 36864 B per tile (4 planes)

// Scratch (no allocation allowed in kernel_launch)
__device__ float g_q[NROWS*DOUT];
__device__ float g_k[NROWS*DOUT];
__device__ float g_v[NROWS*DOUT];
__device__ float g_pacc[(size_t)NPART*128*DOUT];
__device__ float g_pl[NPART*128];
// Pre-split weights (fp16 hi/lo): [mat][n][k], k-contiguous
__device__ __half g_wt_hi[3*64*1024];
__device__ __half g_wt_lo[3*64*1024];
// Pre-converted KV tiles (fp16 hi/lo): [b*64+kt][plane][4608]
//   plane 0 = K hi [key][d], 1 = K lo, 2 = Vt hi [d][key], 3 = Vt lo
__device__ __half g_tiles[(size_t)BB*64*4*TILE_ELEMS];

// ---------------------------------------------------------------------------
// fp16 helpers: cvtf2 packs first arg into LOW 16 bits (even element)
// ---------------------------------------------------------------------------
__device__ __forceinline__ uint32_t cvtf2(float lo, float hi) {
    uint32_t r;
    asm("cvt.rn.f16x2.f32 %0, %1, %2;" : "=r"(r) : "f"(hi), "f"(lo));
    return r;
}
__device__ __forceinline__ float2 f16x2_f32(uint32_t h) {
    float lo, hi;
    asm("{ .reg .b16 a, b; mov.b32 {a, b}, %2; "
        "cvt.f32.f16 %0, a; cvt.f32.f16 %1, b; }"
        : "=f"(lo), "=f"(hi) : "r"(h));
    return make_float2(lo, hi);
}

__device__ __forceinline__ uint32_t smem_u32(const void* p) {
    uint32_t a;
    asm("{ .reg .u64 t; cvta.to.shared.u64 t, %1; cvt.u32.u64 %0, t; }"
        : "=r"(a) : "l"(p));
    return a;
}

// mma.sync m16n8k16 row.col f16 -> f32 (sm_80+ PTX; frag layout validated r5-11)
//   A: a0=(g,2t..2t+1) a1=(g+8,2t..) a2=(g,2t+8..) a3=(g+8,2t+8..)
//   B: b0=(n=g, k=2t..2t+1) b1=(n=g, k=2t+8..2t+9)
//   C: c0,c1=(row g, cols 2t,2t+1); c2,c3=(row g+8, cols 2t,2t+1)
__device__ __forceinline__ void mma_f16(float* d, uint32_t a0, uint32_t a1,
                                        uint32_t a2, uint32_t a3,
                                        uint32_t b0, uint32_t b1) {
    asm("mma.sync.aligned.m16n8k16.row.col.f32.f16.f16.f32 "
        "{%0,%1,%2,%3}, {%4,%5,%6,%7}, {%8,%9}, {%0,%1,%2,%3};"
        : "+f"(d[0]), "+f"(d[1]), "+f"(d[2]), "+f"(d[3])
        : "r"(a0), "r"(a1), "r"(a2), "r"(a3), "r"(b0), "r"(b1));
}

// ldmatrix m8n8.x4 (validated r9-r11)
__device__ __forceinline__ void ldm_x4(uint32_t& r0, uint32_t& r1,
                                       uint32_t& r2, uint32_t& r3, uint32_t addr) {
    asm volatile("ldmatrix.sync.aligned.m8n8.x4.shared.b16 {%0,%1,%2,%3}, [%4];"
                 : "=r"(r0), "=r"(r1), "=r"(r2), "=r"(r3) : "r"(addr));
}

// ---------------------------------------------------------------------------
// Kernel 0: split W into fp16 hi/lo, transposed to [mat][n][k]
// ---------------------------------------------------------------------------
__global__ __launch_bounds__(256) void prep_w_kernel(
    const float* __restrict__ Wq, const float* __restrict__ Wk,
    const float* __restrict__ Wv)
{
    int idx = blockIdx.x * 256 + threadIdx.x;     // 0 .. 196607
    int mat = idx >> 16;
    int r   = idx & 65535;
    const float* W = (mat == 0) ? Wq : (mat == 1) ? Wk : Wv;
    float w = W[r];                                // coalesced read: r = k*64+n
    int k = r >> 6;
    int n = r & 63;
    __half hi = __float2half(w);
    __half lo = __float2half(w - __half2float(hi));
    int dst = (mat << 16) + n * 1024 + k;
    g_wt_hi[dst] = hi;
    g_wt_lo[dst] = lo;
}

// ---------------------------------------------------------------------------
// Kernel 1: QKV via mma.sync fp16 2-pass (xh*wh + xh*wl), fp32 accumulate.
// Block = 128 threads (4 warps), warp = 16 rows, block = 64 rows; grid = 256.
// B frags via ldmatrix.x4 (80B row stride).
// ---------------------------------------------------------------------------
#define WTS 40   // f16 elements per smem B row (80B stride)

__global__ __launch_bounds__(128) void qkv_mma_kernel(
    const float* __restrict__ x,
    const float* __restrict__ bq, const float* __restrict__ bk,
    const float* __restrict__ bv)
{
    __shared__ __align__(16) __half bs_hi[3 * 64 * WTS];  // 15360 B
    __shared__ __align__(16) __half bs_lo[3 * 64 * WTS];  // 15360 B

    int tid  = threadIdx.x;
    int wid  = tid >> 5;
    int lane = tid & 31;
    int g    = lane >> 2;     // 0..7
    int t    = lane & 3;      // 0..3
    int r0   = blockIdx.x * 64;
    int rA   = r0 + wid * 16 + g;          // rows rA and rA+8

    uint32_t bhi_base = smem_u32(bs_hi);
    uint32_t blo_base = smem_u32(bs_lo);
    uint32_t laneoff = (((lane >> 4) * 8 + (lane & 7)) * WTS) * 2
                       + (((lane >> 3) & 1) * 8) * 2;

    float acc[3][8][4];
#pragma unroll
    for (int m = 0; m < 3; m++)
#pragma unroll
        for (int nt = 0; nt < 8; nt++)
#pragma unroll
            for (int i = 0; i < 4; i++) acc[m][nt][i] = 0.f;

    const float* xlo = &x[(size_t)rA * DIN];
    const float* xhi = &x[(size_t)(rA + 8) * DIN];

    for (int c0 = 0; c0 < DIN; c0 += 32) {
        __syncthreads();
#pragma unroll
        for (int p = 0; p < 6; p++) {
            int i = tid + p * 128;
            int row = i >> 2;            // 0..191  (= mat*64 + n)
            int cc  = i & 3;             // 16B chunk
            int src = row * 1024 + c0 + cc * 8;
            *(uint4*)&bs_hi[row * WTS + cc * 8] = *(const uint4*)&g_wt_hi[src];
            *(uint4*)&bs_lo[row * WTS + cc * 8] = *(const uint4*)&g_wt_lo[src];
        }
        __syncthreads();

#pragma unroll
        for (int ks = 0; ks < 2; ks++) {
            int kk = c0 + ks * 16;
            float2 xa = *(const float2*)&xlo[kk + 2 * t];
            float2 xb = *(const float2*)&xlo[kk + 2 * t + 8];
            float2 xc = *(const float2*)&xhi[kk + 2 * t];
            float2 xd = *(const float2*)&xhi[kk + 2 * t + 8];
            uint32_t ah0 = cvtf2(xa.x, xa.y);
            uint32_t ah1 = cvtf2(xc.x, xc.y);
            uint32_t ah2 = cvtf2(xb.x, xb.y);
            uint32_t ah3 = cvtf2(xd.x, xd.y);

#pragma unroll
            for (int m = 0; m < 3; m++) {
#pragma unroll
                for (int np = 0; np < 4; np++) {     // nt pair 2np, 2np+1
                    uint32_t off = ((m * 64 + np * 16) * WTS + ks * 16) * 2;
                    uint32_t h0a, h1a, h0b, h1b, l0a, l1a, l0b, l1b;
                    ldm_x4(h0a, h1a, h0b, h1b, bhi_base + off + laneoff);
                    ldm_x4(l0a, l1a, l0b, l1b, blo_base + off + laneoff);
                    mma_f16(acc[m][2*np],   ah0, ah1, ah2, ah3, h0a, h1a);
                    mma_f16(acc[m][2*np],   ah0, ah1, ah2, ah3, l0a, l1a);
                    mma_f16(acc[m][2*np+1], ah0, ah1, ah2, ah3, h0b, h1b);
                    mma_f16(acc[m][2*np+1], ah0, ah1, ah2, ah3, l0b, l1b);
                }
            }
        }
    }

#pragma unroll
    for (int m = 0; m < 3; m++) {
        float* out = (m == 0) ? g_q : (m == 1) ? g_k : g_v;
        const float* bias = (m == 0) ? bq : (m == 1) ? bk : bv;
#pragma unroll
        for (int nt = 0; nt < 8; nt++) {
            int col = nt * 8 + 2 * t;
            float b0 = bias[col], b1 = bias[col + 1];
            float2 o0 = make_float2(acc[m][nt][0] + b0, acc[m][nt][1] + b1);
            float2 o1 = make_float2(acc[m][nt][2] + b0, acc[m][nt][3] + b1);
            *(float2*)&out[(size_t)rA * DOUT + col] = o0;
            *(float2*)&out[(size_t)(rA + 8) * DOUT + col] = o1;
        }
    }
}

// ---------------------------------------------------------------------------
// Kernel 1b: pre-convert K/V into fp16 hi/lo tile images (UNCHANGED from r11)
// ---------------------------------------------------------------------------
__global__ __launch_bounds__(256) void preconv_kernel()
{
    __shared__ float vsm[64 * 65];

    int bt  = blockIdx.x;             // b*64 + kt
    int b   = bt >> 6;
    int kt  = bt & 63;
    int tid = threadIdx.x;

    __half* tk_hi = &g_tiles[((size_t)bt * 4 + 0) * TILE_ELEMS];
    __half* tk_lo = &g_tiles[((size_t)bt * 4 + 1) * TILE_ELEMS];
    __half* tv_hi = &g_tiles[((size_t)bt * 4 + 2) * TILE_ELEMS];
    __half* tv_lo = &g_tiles[((size_t)bt * 4 + 3) * TILE_ELEMS];

#pragma unroll
    for (int p = 0; p < 4; p++) {
        int idx4 = tid + p * 256;            // 0..1023 float4s
        int key  = idx4 >> 4;
        int dq   = (idx4 & 15) * 4;
        size_t gsrc = ((size_t)b * SS + kt * 64 + key) * DOUT + dq;

        float4 kv = *(const float4*)&g_k[gsrc];
        uint32_t h0 = cvtf2(kv.x, kv.y), h1 = cvtf2(kv.z, kv.w);
        float2 hb0 = f16x2_f32(h0), hb1 = f16x2_f32(h1);
        uint32_t l0 = cvtf2(kv.x - hb0.x, kv.y - hb0.y);
        uint32_t l1 = cvtf2(kv.z - hb1.x, kv.w - hb1.y);
        *(uint2*)&tk_hi[key * KST + dq] = make_uint2(h0, h1);
        *(uint2*)&tk_lo[key * KST + dq] = make_uint2(l0, l1);

        float4 vv = *(const float4*)&g_v[gsrc];
        vsm[key * 65 + dq + 0] = vv.x;
        vsm[key * 65 + dq + 1] = vv.y;
        vsm[key * 65 + dq + 2] = vv.z;
        vsm[key * 65 + dq + 3] = vv.w;
    }
    __syncthreads();

    {
        int d  = tid >> 2;
        int kq = (tid & 3) * 16;
        uint32_t h[8], l[8];
#pragma unroll
        for (int i = 0; i < 8; i++) {
            float f0 = vsm[(kq + 2 * i) * 65 + d];
            float f1 = vsm[(kq + 2 * i + 1) * 65 + d];
            h[i] = cvtf2(f0, f1);
            float2 hb = f16x2_f32(h[i]);
            l[i] = cvtf2(f0 - hb.x, f1 - hb.y);
        }
        uint4* dsth = (uint4*)&tv_hi[d * KST + kq];
        uint4* dstl = (uint4*)&tv_lo[d * KST + kq];
        dsth[0] = make_uint4(h[0], h[1], h[2], h[3]);
        dsth[1] = make_uint4(h[4], h[5], h[6], h[7]);
        dstl[0] = make_uint4(l[0], l[1], l[2], l[3]);
        dstl[1] = make_uint4(l[4], l[5], l[6], l[7]);
    }
}

// ---------------------------------------------------------------------------
// Kernel 2: flash-attention partial, fp16 2-pass (UNCHANGED from r11; 61us)
// ---------------------------------------------------------------------------
__global__ __launch_bounds__(256, 2) void attn_mma_kernel()
{
    extern __shared__ __align__(16) char smdyn[];

    int blk = blockIdx.x;
    int b   = blk / (NQT * MAXCH);
    int rem = blk % (NQT * MAXCH);
    int qt  = rem / MAXCH;
    int ch  = rem % MAXCH;
    int nch = (qt >> 2) + 1;   // ceil((qt+1)*128 / 512)
    if (ch >= nch) return;

    int tid  = threadIdx.x;
    int w    = tid >> 5;
    int lane = tid & 31;
    int g    = lane >> 2;
    int t    = lane & 3;

    int rg  = qt * 128 + w * 16 + g;   // query rows rg and rg+8
    int rg8 = rg + 8;

    uint32_t smT_base = smem_u32(smdyn);
    uint32_t laneoff = ((((lane >> 4) * 8 + (lane & 7)) * KST
                         + ((lane >> 3) & 1) * 8) * 2);

    // Q fragments (scale folded in), fp16 hi only
    const float SCALE = 0.015625f;   // 1/sqrt(4096)
    uint32_t qh[4][4];
    {
        const float* q0 = &g_q[((size_t)b * SS + rg) * DOUT];
        const float* q8 = &g_q[((size_t)b * SS + rg8) * DOUT];
#pragma unroll
        for (int ks = 0; ks < 4; ks++) {
            float2 xa = *(const float2*)&q0[ks * 16 + 2 * t];
            float2 xc = *(const float2*)&q8[ks * 16 + 2 * t];
            float2 xb = *(const float2*)&q0[ks * 16 + 2 * t + 8];
            float2 xd = *(const float2*)&q8[ks * 16 + 2 * t + 8];
            qh[ks][0] = cvtf2(xa.x * SCALE, xa.y * SCALE);
            qh[ks][1] = cvtf2(xc.x * SCALE, xc.y * SCALE);
            qh[ks][2] = cvtf2(xb.x * SCALE, xb.y * SCALE);
            qh[ks][3] = cvtf2(xd.x * SCALE, xd.y * SCALE);
        }
    }

    float o[8][4];
#pragma unroll
    for (int nd = 0; nd < 8; nd++)
#pragma unroll
        for (int i = 0; i < 4; i++) o[nd][i] = 0.f;
    float lg = 0.f, lg8 = 0.f;

    int k0 = ch * CHUNK;
    int k1 = min(k0 + CHUNK, (qt + 1) * 128);

    // ---- prologue: stage first tile into buffer 0
    {
        const char* src =
            (const char*)&g_tiles[((size_t)(b * 64 + (k0 >> 6)) * 4) * TILE_ELEMS];
#pragma unroll
        for (int p = 0; p < 9; p++) {
            int i = tid + p * 256;
            asm volatile("cp.async.cg.shared.global [%0], [%1], 16;"
                         :: "r"(smT_base + i * 16), "l"(src + (size_t)i * 16)
                         : "memory");
        }
        asm volatile("cp.async.commit_group;" ::: "memory");
    }

    int ib = 0;
    for (int kt = k0; kt < k1; kt += 64, ib ^= 1) {
        int ktn = kt + 64;
        if (ktn < k1) {
            uint32_t nb = smT_base + (ib ^ 1) * TILE_BYTES;
            const char* src =
                (const char*)&g_tiles[((size_t)(b * 64 + (ktn >> 6)) * 4) * TILE_ELEMS];
#pragma unroll
            for (int p = 0; p < 9; p++) {
                int i = tid + p * 256;
                asm volatile("cp.async.cg.shared.global [%0], [%1], 16;"
                             :: "r"(nb + i * 16), "l"(src + (size_t)i * 16)
                             : "memory");
            }
            asm volatile("cp.async.commit_group;" ::: "memory");
            asm volatile("cp.async.wait_group 1;" ::: "memory");
        } else {
            asm volatile("cp.async.wait_group 0;" ::: "memory");
        }
        __syncthreads();

        uint32_t bufb  = smT_base + ib * TILE_BYTES;
        uint32_t aK_hi = bufb + 0 * TILE_ELEMS * 2 + laneoff;
        uint32_t aK_lo = bufb + 1 * TILE_ELEMS * 2 + laneoff;
        uint32_t aV_hi = bufb + 2 * TILE_ELEMS * 2 + laneoff;
        uint32_t aV_lo = bufb + 3 * TILE_ELEMS * 2 + laneoff;

        // ---- QK^T: 2-pass fp16 (qh*kh + qh*kl), fp32 C
        float c[8][4];
#pragma unroll
        for (int nc = 0; nc < 8; nc++)
#pragma unroll
            for (int i = 0; i < 4; i++) c[nc][i] = 0.f;

#pragma unroll
        for (int ks = 0; ks < 4; ks++) {
#pragma unroll
            for (int np = 0; np < 4; np++) {     // nc pair 2np, 2np+1
                uint32_t off = (np * 16 * KST + ks * 16) * 2;
                uint32_t h0a, h1a, h0b, h1b, l0a, l1a, l0b, l1b;
                ldm_x4(h0a, h1a, h0b, h1b, aK_hi + off);
                ldm_x4(l0a, l1a, l0b, l1b, aK_lo + off);
                mma_f16(c[2*np],   qh[ks][0], qh[ks][1], qh[ks][2], qh[ks][3], h0a, h1a);
                mma_f16(c[2*np],   qh[ks][0], qh[ks][1], qh[ks][2], qh[ks][3], l0a, l1a);
                mma_f16(c[2*np+1], qh[ks][0], qh[ks][1], qh[ks][2], qh[ks][3], h0b, h1b);
                mma_f16(c[2*np+1], qh[ks][0], qh[ks][1], qh[ks][2], qh[ks][3], l0b, l1b);
            }
        }

        // ---- masked exp; pack P (fp16 hi only) into PV A-fragments
        uint32_t pah[4][4];
#pragma unroll
        for (int nc = 0; nc < 8; nc++) {
            int col0 = kt + nc * 8 + 2 * t;
            int col1 = col0 + 1;
            float e0 = (col0 <= rg)  ? __expf(c[nc][0]) : 0.f;
            float e1 = (col1 <= rg)  ? __expf(c[nc][1]) : 0.f;
            float e2 = (col0 <= rg8) ? __expf(c[nc][2]) : 0.f;
            float e3 = (col1 <= rg8) ? __expf(c[nc][3]) : 0.f;
            lg  += e0 + e1;
            lg8 += e2 + e3;
            uint32_t h01 = cvtf2(e0, e1), h23 = cvtf2(e2, e3);
            int j = nc >> 1;
            if ((nc & 1) == 0) { pah[j][0] = h01; pah[j][1] = h23; }
            else               { pah[j][2] = h01; pah[j][3] = h23; }
        }

        // ---- PV: 2-pass fp16 (ph*vh + ph*vl)
#pragma unroll
        for (int j = 0; j < 4; j++) {
#pragma unroll
            for (int np = 0; np < 4; np++) {     // nd pair 2np, 2np+1
                uint32_t off = (np * 16 * KST + j * 16) * 2;
                uint32_t h0a, h1a, h0b, h1b, l0a, l1a, l0b, l1b;
                ldm_x4(h0a, h1a, h0b, h1b, aV_hi + off);
                ldm_x4(l0a, l1a, l0b, l1b, aV_lo + off);
                mma_f16(o[2*np],   pah[j][0], pah[j][1], pah[j][2], pah[j][3], h0a, h1a);
                mma_f16(o[2*np],   pah[j][0], pah[j][1], pah[j][2], pah[j][3], l0a, l1a);
                mma_f16(o[2*np+1], pah[j][0], pah[j][1], pah[j][2], pah[j][3], h0b, h1b);
                mma_f16(o[2*np+1], pah[j][0], pah[j][1], pah[j][2], pah[j][3], l0b, l1b);
            }
        }
        __syncthreads();   // all reads of buf ib done before next prefetch overwrites it
    }

    // ---- l reduce across the t-quad (lanes g*4 + t)
    lg  += __shfl_xor_sync(0xffffffffu, lg, 1);
    lg  += __shfl_xor_sync(0xffffffffu, lg, 2);
    lg8 += __shfl_xor_sync(0xffffffffu, lg8, 1);
    lg8 += __shfl_xor_sync(0xffffffffu, lg8, 2);

    int pidx = (b * NQT + qt) * MAXCH + ch;
    int rl = w * 16 + g;
    if (t == 0) {
        g_pl[pidx * 128 + rl]     = lg;
        g_pl[pidx * 128 + rl + 8] = lg8;
    }
    float* pa0 = &g_pacc[((size_t)pidx * 128 + rl) * DOUT];
    float* pa8 = &g_pacc[((size_t)pidx * 128 + rl + 8) * DOUT];
#pragma unroll
    for (int nd = 0; nd < 8; nd++) {
        *(float2*)&pa0[nd * 8 + 2 * t] = make_float2(o[nd][0], o[nd][1]);
        *(float2*)&pa8[nd * 8 + 2 * t] = make_float2(o[nd][2], o[nd][3]);
    }
}

// ---------------------------------------------------------------------------
// Kernel 3: combine split-KV partials. 256 threads = 4 rows x 64 dims.
// grid = B*S/4 blocks.
// ---------------------------------------------------------------------------
__global__ __launch_bounds__(256) void combine_kernel(float* __restrict__ out)
{
    int rowg = blockIdx.x * 4 + (threadIdx.x >> 6);
    int b    = rowg / SS;
    int row  = rowg % SS;
    int qt   = row >> 7;
    int r    = row & 127;
    int nch  = (qt >> 2) + 1;
    int d    = threadIdx.x & 63;
    int pbase = (b * NQT + qt) * MAXCH;

    float L = 0.f, o = 0.f;
    for (int c = 0; c < nch; c++) {
        L += g_pl[(pbase + c) * 128 + r];
        o += g_pacc[((size_t)(pbase + c) * 128 + r) * DOUT + d];
    }
    out[((size_t)b * SS + row) * DOUT + d] = o / L;
}

// ---------------------------------------------------------------------------
extern "C" void kernel_launch(void* const* d_in, const int* in_sizes, int n_in,
                              void* d_out, int out_size)
{
    const float* x  = (const float*)d_in[0];
    const float* Wq = (const float*)d_in[1];
    const float* bq = (const float*)d_in[2];
    const float* Wk = (const float*)d_in[3];
    const float* bk = (const float*)d_in[4];
    const float* Wv = (const float*)d_in[5];
    const float* bv = (const float*)d_in[6];
    float* out = (float*)d_out;

    cudaFuncSetAttribute(attn_mma_kernel,
                         cudaFuncAttributeMaxDynamicSharedMemorySize,
                         2 * TILE_BYTES);

    prep_w_kernel<<<768, 256>>>(Wq, Wk, Wv);
    qkv_mma_kernel<<<NROWS / 64, 128>>>(x, bq, bk, bv);
    preconv_kernel<<<BB * 64, 256>>>();
    attn_mma_kernel<<<NPART, 256, 2 * TILE_BYTES>>>();
    combine_kernel<<<BB * SS / 4, 256>>>(out);
}

// round 13
// speedup vs baseline: 1.7436x; 1.5197x over previous
#include <cuda_runtime.h>
#include <cuda_fp16.h>
#include <math.h>
#include <stdint.h>

#define BB 4
#define SS 4096
#define DIN 1024
#define DOUT 64
#define NROWS (BB*SS)          // 16384

#define NQT (SS/128)           // 32 query tiles of 128 rows per batch
#define CHUNK 512              // keys per split-KV chunk
#define MAXCH 8
#define NPART (BB*NQT*MAXCH)   // 1024

#define KST 72                 // tile row stride (f16 elems)
#define PLANE_ELEMS (64*KST)   // 4608 per plane
#define TILE2_BYTES (2*PLANE_ELEMS*2)   // 18432 B per tile (K hi + Vt hi)

// Scratch (no allocation allowed in kernel_launch)
__device__ float g_q[NROWS*DOUT];
__device__ float g_k[NROWS*DOUT];
__device__ float g_v[NROWS*DOUT];
__device__ float g_pacc[(size_t)NPART*128*DOUT];
__device__ float g_pl[NPART*128];
// Pre-split weights (fp16): [mat][n][k], k-contiguous
__device__ __half g_wt[3*64*1024];
// Pre-converted KV tiles (fp16): [b*64+kt][plane][4608]
//   plane 0 = K [key][d], 1 = Vt [d][key]
__device__ __half g_tiles[(size_t)BB*64*2*PLANE_ELEMS];

// ---------------------------------------------------------------------------
// fp16 helpers: cvtf2 packs first arg into LOW 16 bits (even element)
// ---------------------------------------------------------------------------
__device__ __forceinline__ uint32_t cvtf2(float lo, float hi) {
    uint32_t r;
    asm("cvt.rn.f16x2.f32 %0, %1, %2;" : "=r"(r) : "f"(hi), "f"(lo));
    return r;
}

__device__ __forceinline__ uint32_t smem_u32(const void* p) {
    uint32_t a;
    asm("{ .reg .u64 t; cvta.to.shared.u64 t, %1; cvt.u32.u64 %0, t; }"
        : "=r"(a) : "l"(p));
    return a;
}

// mma.sync m16n8k16 row.col f16 -> f32 (sm_80+ PTX; frag layout validated r5-12)
//   A: a0=(g,2t..2t+1) a1=(g+8,2t..) a2=(g,2t+8..) a3=(g+8,2t+8..)
//   B: b0=(n=g, k=2t..2t+1) b1=(n=g, k=2t+8..2t+9)
//   C: c0,c1=(row g, cols 2t,2t+1); c2,c3=(row g+8, cols 2t,2t+1)
__device__ __forceinline__ void mma_f16(float* d, uint32_t a0, uint32_t a1,
                                        uint32_t a2, uint32_t a3,
                                        uint32_t b0, uint32_t b1) {
    asm("mma.sync.aligned.m16n8k16.row.col.f32.f16.f16.f32 "
        "{%0,%1,%2,%3}, {%4,%5,%6,%7}, {%8,%9}, {%0,%1,%2,%3};"
        : "+f"(d[0]), "+f"(d[1]), "+f"(d[2]), "+f"(d[3])
        : "r"(a0), "r"(a1), "r"(a2), "r"(a3), "r"(b0), "r"(b1));
}

// ldmatrix m8n8.x4 (validated r9-r12)
__device__ __forceinline__ void ldm_x4(uint32_t& r0, uint32_t& r1,
                                       uint32_t& r2, uint32_t& r3, uint32_t addr) {
    asm volatile("ldmatrix.sync.aligned.m8n8.x4.shared.b16 {%0,%1,%2,%3}, [%4];"
                 : "=r"(r0), "=r"(r1), "=r"(r2), "=r"(r3) : "r"(addr));
}

// ---------------------------------------------------------------------------
// Kernel 0: convert W to fp16, transposed to [mat][n][k] (k-contiguous)
// ---------------------------------------------------------------------------
__global__ __launch_bounds__(256) void prep_w_kernel(
    const float* __restrict__ Wq, const float* __restrict__ Wk,
    const float* __restrict__ Wv)
{
    int idx = blockIdx.x * 256 + threadIdx.x;     // 0 .. 196607
    int mat = idx >> 16;
    int r   = idx & 65535;
    const float* W = (mat == 0) ? Wq : (mat == 1) ? Wk : Wv;
    float w = W[r];                                // coalesced read: r = k*64+n
    int k = r >> 6;
    int n = r & 63;
    g_wt[(mat << 16) + n * 1024 + k] = __float2half(w);
}

// ---------------------------------------------------------------------------
// Kernel 1: QKV via mma.sync fp16 single-pass, fp32 accumulate.
// grid (256, 3): one matrix per block, 64 rows, 128 threads (4 warps).
// Double-buffered cp.async B staging (4KB/chunk), ldmatrix B frags.
// ---------------------------------------------------------------------------
#define QWTS 40   // f16 elements per smem B row (80B stride)
#define QBUF (64*QWTS)   // 2560 halves = 5120 B per buffer

__global__ __launch_bounds__(128) void qkv_mma_kernel(
    const float* __restrict__ x,
    const float* __restrict__ bq, const float* __restrict__ bk,
    const float* __restrict__ bv)
{
    __shared__ __align__(16) __half bs[2 * QBUF];   // 10240 B

    int tid  = threadIdx.x;
    int wid  = tid >> 5;
    int lane = tid & 31;
    int g    = lane >> 2;     // 0..7
    int t    = lane & 3;      // 0..3
    int mat  = blockIdx.y;
    int r0   = blockIdx.x * 64;
    int rA   = r0 + wid * 16 + g;          // rows rA and rA+8

    const __half* wsrc = &g_wt[mat << 16];
    float* out = (mat == 0) ? g_q : (mat == 1) ? g_k : g_v;
    const float* bias = (mat == 0) ? bq : (mat == 1) ? bk : bv;

    uint32_t bbase = smem_u32(bs);
    uint32_t laneoff = (((lane >> 4) * 8 + (lane & 7)) * QWTS) * 2
                       + (((lane >> 3) & 1) * 8) * 2;

    float acc[8][4];
#pragma unroll
    for (int nt = 0; nt < 8; nt++)
#pragma unroll
        for (int i = 0; i < 4; i++) acc[nt][i] = 0.f;

    const float* xlo = &x[(size_t)rA * DIN];
    const float* xhi = &x[(size_t)(rA + 8) * DIN];

    // prologue: stage chunk 0 into buffer 0 (256 uint4 = 4096B of W data)
#pragma unroll
    for (int i = tid; i < 256; i += 128) {
        int row = i >> 2;
        int cc  = i & 3;
        asm volatile("cp.async.cg.shared.global [%0], [%1], 16;"
                     :: "r"(bbase + (row * QWTS + cc * 8) * 2),
                        "l"((const char*)&wsrc[row * 1024 + cc * 8])
                     : "memory");
    }
    asm volatile("cp.async.commit_group;" ::: "memory");

    int ib = 0;
    for (int c = 0; c < 32; c++, ib ^= 1) {
        if (c + 1 < 32) {
            int c0n = (c + 1) * 32;
            uint32_t nb = bbase + (ib ^ 1) * QBUF * 2;
#pragma unroll
            for (int i = tid; i < 256; i += 128) {
                int row = i >> 2;
                int cc  = i & 3;
                asm volatile("cp.async.cg.shared.global [%0], [%1], 16;"
                             :: "r"(nb + (row * QWTS + cc * 8) * 2),
                                "l"((const char*)&wsrc[row * 1024 + c0n + cc * 8])
                             : "memory");
            }
            asm volatile("cp.async.commit_group;" ::: "memory");
            asm volatile("cp.async.wait_group 1;" ::: "memory");
        } else {
            asm volatile("cp.async.wait_group 0;" ::: "memory");
        }
        __syncthreads();

        uint32_t bufb = bbase + ib * QBUF * 2;
        int c0 = c * 32;
#pragma unroll
        for (int ks = 0; ks < 2; ks++) {
            int kk = c0 + ks * 16;
            float2 xa = *(const float2*)&xlo[kk + 2 * t];
            float2 xb = *(const float2*)&xlo[kk + 2 * t + 8];
            float2 xc = *(const float2*)&xhi[kk + 2 * t];
            float2 xd = *(const float2*)&xhi[kk + 2 * t + 8];
            uint32_t a0 = cvtf2(xa.x, xa.y);
            uint32_t a1 = cvtf2(xc.x, xc.y);
            uint32_t a2 = cvtf2(xb.x, xb.y);
            uint32_t a3 = cvtf2(xd.x, xd.y);

#pragma unroll
            for (int np = 0; np < 4; np++) {     // nt pair 2np, 2np+1
                uint32_t off = (np * 16 * QWTS + ks * 16) * 2;
                uint32_t b0a, b1a, b0b, b1b;
                ldm_x4(b0a, b1a, b0b, b1b, bufb + off + laneoff);
                mma_f16(acc[2*np],   a0, a1, a2, a3, b0a, b1a);
                mma_f16(acc[2*np+1], a0, a1, a2, a3, b0b, b1b);
            }
        }
        __syncthreads();
    }

#pragma unroll
    for (int nt = 0; nt < 8; nt++) {
        int col = nt * 8 + 2 * t;
        float b0 = bias[col], b1 = bias[col + 1];
        float2 o0 = make_float2(acc[nt][0] + b0, acc[nt][1] + b1);
        float2 o1 = make_float2(acc[nt][2] + b0, acc[nt][3] + b1);
        *(float2*)&out[(size_t)rA * DOUT + col] = o0;
        *(float2*)&out[(size_t)(rA + 8) * DOUT + col] = o1;
    }
}

// ---------------------------------------------------------------------------
// Kernel 1b: pre-convert K/V into fp16 tile images (2 planes: K, Vt)
// ---------------------------------------------------------------------------
__global__ __launch_bounds__(256) void preconv_kernel()
{
    __shared__ float vsm[64 * 65];

    int bt  = blockIdx.x;             // b*64 + kt
    int b   = bt >> 6;
    int kt  = bt & 63;
    int tid = threadIdx.x;

    __half* tk = &g_tiles[(size_t)bt * 2 * PLANE_ELEMS];
    __half* tv = tk + PLANE_ELEMS;

#pragma unroll
    for (int p = 0; p < 4; p++) {
        int idx4 = tid + p * 256;            // 0..1023 float4s
        int key  = idx4 >> 4;
        int dq   = (idx4 & 15) * 4;
        size_t gsrc = ((size_t)b * SS + kt * 64 + key) * DOUT + dq;

        float4 kv = *(const float4*)&g_k[gsrc];
        uint32_t h0 = cvtf2(kv.x, kv.y), h1 = cvtf2(kv.z, kv.w);
        *(uint2*)&tk[key * KST + dq] = make_uint2(h0, h1);

        float4 vv = *(const float4*)&g_v[gsrc];
        vsm[key * 65 + dq + 0] = vv.x;
        vsm[key * 65 + dq + 1] = vv.y;
        vsm[key * 65 + dq + 2] = vv.z;
        vsm[key * 65 + dq + 3] = vv.w;
    }
    __syncthreads();

    {
        int d  = tid >> 2;
        int kq = (tid & 3) * 16;
        uint32_t h[8];
#pragma unroll
        for (int i = 0; i < 8; i++) {
            h[i] = cvtf2(vsm[(kq + 2 * i) * 65 + d],
                         vsm[(kq + 2 * i + 1) * 65 + d]);
        }
        uint4* dst = (uint4*)&tv[d * KST + kq];
        dst[0] = make_uint4(h[0], h[1], h[2], h[3]);
        dst[1] = make_uint4(h[4], h[5], h[6], h[7]);
    }
}

// ---------------------------------------------------------------------------
// Kernel 2: flash-attention partial, fully fp16 single-pass.
// Double-buffered 18KB tile staging, ldmatrix B frags.
// ---------------------------------------------------------------------------
__global__ __launch_bounds__(256, 2) void attn_mma_kernel()
{
    extern __shared__ __align__(16) char smdyn[];

    int blk = blockIdx.x;
    int b   = blk / (NQT * MAXCH);
    int rem = blk % (NQT * MAXCH);
    int qt  = rem / MAXCH;
    int ch  = rem % MAXCH;
    int nch = (qt >> 2) + 1;   // ceil((qt+1)*128 / 512)
    if (ch >= nch) return;

    int tid  = threadIdx.x;
    int w    = tid >> 5;
    int lane = tid & 31;
    int g    = lane >> 2;
    int t    = lane & 3;

    int rg  = qt * 128 + w * 16 + g;   // query rows rg and rg+8
    int rg8 = rg + 8;

    uint32_t smT_base = smem_u32(smdyn);
    uint32_t laneoff = ((((lane >> 4) * 8 + (lane & 7)) * KST
                         + ((lane >> 3) & 1) * 8) * 2);

    // Q fragments (scale folded in), fp16
    const float SCALE = 0.015625f;   // 1/sqrt(4096)
    uint32_t qh[4][4];
    {
        const float* q0 = &g_q[((size_t)b * SS + rg) * DOUT];
        const float* q8 = &g_q[((size_t)b * SS + rg8) * DOUT];
#pragma unroll
        for (int ks = 0; ks < 4; ks++) {
            float2 xa = *(const float2*)&q0[ks * 16 + 2 * t];
            float2 xc = *(const float2*)&q8[ks * 16 + 2 * t];
            float2 xb = *(const float2*)&q0[ks * 16 + 2 * t + 8];
            float2 xd = *(const float2*)&q8[ks * 16 + 2 * t + 8];
            qh[ks][0] = cvtf2(xa.x * SCALE, xa.y * SCALE);
            qh[ks][1] = cvtf2(xc.x * SCALE, xc.y * SCALE);
            qh[ks][2] = cvtf2(xb.x * SCALE, xb.y * SCALE);
            qh[ks][3] = cvtf2(xd.x * SCALE, xd.y * SCALE);
        }
    }

    float o[8][4];
#pragma unroll
    for (int nd = 0; nd < 8; nd++)
#pragma unroll
        for (int i = 0; i < 4; i++) o[nd][i] = 0.f;
    float lg = 0.f, lg8 = 0.f;

    int k0 = ch * CHUNK;
    int k1 = min(k0 + CHUNK, (qt + 1) * 128);

    // ---- prologue: stage first tile (1152 uint4 = 18432B) into buffer 0
    {
        const char* src =
            (const char*)&g_tiles[(size_t)(b * 64 + (k0 >> 6)) * 2 * PLANE_ELEMS];
        for (int i = tid; i < 1152; i += 256) {
            asm volatile("cp.async.cg.shared.global [%0], [%1], 16;"
                         :: "r"(smT_base + i * 16), "l"(src + (size_t)i * 16)
                         : "memory");
        }
        asm volatile("cp.async.commit_group;" ::: "memory");
    }

    int ib = 0;
    for (int kt = k0; kt < k1; kt += 64, ib ^= 1) {
        int ktn = kt + 64;
        if (ktn < k1) {
            uint32_t nb = smT_base + (ib ^ 1) * TILE2_BYTES;
            const char* src =
                (const char*)&g_tiles[(size_t)(b * 64 + (ktn >> 6)) * 2 * PLANE_ELEMS];
            for (int i = tid; i < 1152; i += 256) {
                asm volatile("cp.async.cg.shared.global [%0], [%1], 16;"
                             :: "r"(nb + i * 16), "l"(src + (size_t)i * 16)
                             : "memory");
            }
            asm volatile("cp.async.commit_group;" ::: "memory");
            asm volatile("cp.async.wait_group 1;" ::: "memory");
        } else {
            asm volatile("cp.async.wait_group 0;" ::: "memory");
        }
        __syncthreads();

        uint32_t bufb = smT_base + ib * TILE2_BYTES;
        uint32_t aK = bufb + laneoff;
        uint32_t aV = bufb + PLANE_ELEMS * 2 + laneoff;

        // ---- QK^T: single-pass fp16, fp32 C
        float c[8][4];
#pragma unroll
        for (int nc = 0; nc < 8; nc++)
#pragma unroll
            for (int i = 0; i < 4; i++) c[nc][i] = 0.f;

#pragma unroll
        for (int ks = 0; ks < 4; ks++) {
#pragma unroll
            for (int np = 0; np < 4; np++) {     // nc pair 2np, 2np+1
                uint32_t off = (np * 16 * KST + ks * 16) * 2;
                uint32_t b0a, b1a, b0b, b1b;
                ldm_x4(b0a, b1a, b0b, b1b, aK + off);
                mma_f16(c[2*np],   qh[ks][0], qh[ks][1], qh[ks][2], qh[ks][3], b0a, b1a);
                mma_f16(c[2*np+1], qh[ks][0], qh[ks][1], qh[ks][2], qh[ks][3], b0b, b1b);
            }
        }

        // ---- masked exp; pack P (fp16) into PV A-fragments
        uint32_t pah[4][4];
#pragma unroll
        for (int nc = 0; nc < 8; nc++) {
            int col0 = kt + nc * 8 + 2 * t;
            int col1 = col0 + 1;
            float e0 = (col0 <= rg)  ? __expf(c[nc][0]) : 0.f;
            float e1 = (col1 <= rg)  ? __expf(c[nc][1]) : 0.f;
            float e2 = (col0 <= rg8) ? __expf(c[nc][2]) : 0.f;
            float e3 = (col1 <= rg8) ? __expf(c[nc][3]) : 0.f;
            lg  += e0 + e1;
            lg8 += e2 + e3;
            uint32_t h01 = cvtf2(e0, e1), h23 = cvtf2(e2, e3);
            int j = nc >> 1;
            if ((nc & 1) == 0) { pah[j][0] = h01; pah[j][1] = h23; }
            else               { pah[j][2] = h01; pah[j][3] = h23; }
        }

        // ---- PV: single-pass fp16
#pragma unroll
        for (int j = 0; j < 4; j++) {
#pragma unroll
            for (int np = 0; np < 4; np++) {     // nd pair 2np, 2np+1
                uint32_t off = (np * 16 * KST + j * 16) * 2;
                uint32_t b0a, b1a, b0b, b1b;
                ldm_x4(b0a, b1a, b0b, b1b, aV + off);
                mma_f16(o[2*np],   pah[j][0], pah[j][1], pah[j][2], pah[j][3], b0a, b1a);
                mma_f16(o[2*np+1], pah[j][0], pah[j][1], pah[j][2], pah[j][3], b0b, b1b);
            }
        }
        __syncthreads();   // reads of buf ib done before next prefetch overwrites
    }

    // ---- l reduce across the t-quad (lanes g*4 + t)
    lg  += __shfl_xor_sync(0xffffffffu, lg, 1);
    lg  += __shfl_xor_sync(0xffffffffu, lg, 2);
    lg8 += __shfl_xor_sync(0xffffffffu, lg8, 1);
    lg8 += __shfl_xor_sync(0xffffffffu, lg8, 2);

    int pidx = (b * NQT + qt) * MAXCH + ch;
    int rl = w * 16 + g;
    if (t == 0) {
        g_pl[pidx * 128 + rl]     = lg;
        g_pl[pidx * 128 + rl + 8] = lg8;
    }
    float* pa0 = &g_pacc[((size_t)pidx * 128 + rl) * DOUT];
    float* pa8 = &g_pacc[((size_t)pidx * 128 + rl + 8) * DOUT];
#pragma unroll
    for (int nd = 0; nd < 8; nd++) {
        *(float2*)&pa0[nd * 8 + 2 * t] = make_float2(o[nd][0], o[nd][1]);
        *(float2*)&pa8[nd * 8 + 2 * t] = make_float2(o[nd][2], o[nd][3]);
    }
}

// ---------------------------------------------------------------------------
// Kernel 3: combine split-KV partials. 256 threads = 4 rows x 64 dims.
// ---------------------------------------------------------------------------
__global__ __launch_bounds__(256) void combine_kernel(float* __restrict__ out)
{
    int rowg = blockIdx.x * 4 + (threadIdx.x >> 6);
    int b    = rowg / SS;
    int row  = rowg % SS;
    int qt   = row >> 7;
    int r    = row & 127;
    int nch  = (qt >> 2) + 1;
    int d    = threadIdx.x & 63;
    int pbase = (b * NQT + qt) * MAXCH;

    float L = 0.f, o = 0.f;
    for (int c = 0; c < nch; c++) {
        L += g_pl[(pbase + c) * 128 + r];
        o += g_pacc[((size_t)(pbase + c) * 128 + r) * DOUT + d];
    }
    out[((size_t)b * SS + row) * DOUT + d] = o / L;
}

// ---------------------------------------------------------------------------
extern "C" void kernel_launch(void* const* d_in, const int* in_sizes, int n_in,
                              void* d_out, int out_size)
{
    const float* x  = (const float*)d_in[0];
    const float* Wq = (const float*)d_in[1];
    const float* bq = (const float*)d_in[2];
    const float* Wk = (const float*)d_in[3];
    const float* bk = (const float*)d_in[4];
    const float* Wv = (const float*)d_in[5];
    const float* bv = (const float*)d_in[6];
    float* out = (float*)d_out;

    cudaFuncSetAttribute(attn_mma_kernel,
                         cudaFuncAttributeMaxDynamicSharedMemorySize,
                         2 * TILE2_BYTES);

    prep_w_kernel<<<768, 256>>>(Wq, Wk, Wv);
    dim3 gq(NROWS / 64, 3);
    qkv_mma_kernel<<<gq, 128>>>(x, bq, bk, bv);
    preconv_kernel<<<BB * 64, 256>>>();
    attn_mma_kernel<<<NPART, 256, 2 * TILE2_BYTES>>>();
    combine_kernel<<<BB * SS / 4, 256>>>(out);
}

// round 14
// speedup vs baseline: 1.7727x; 1.0167x over previous
#include <cuda_runtime.h>
#include <cuda_fp16.h>
#include <math.h>
#include <stdint.h>

#define BB 4
#define SS 4096
#define DIN 1024
#define DOUT 64
#define NROWS (BB*SS)          // 16384

#define NQT (SS/128)           // 32 query tiles of 128 rows per batch
#define CHUNK 512              // keys per split-KV chunk
#define MAXCH 8
#define NPART (BB*NQT*MAXCH)   // 1024

#define KST 72                 // tile row stride (f16 elems)
#define PLANE_ELEMS (64*KST)   // 4608 per plane
#define TILE2_BYTES (2*PLANE_ELEMS*2)   // 18432 B per tile (K + Vt)

// Scratch (no allocation allowed in kernel_launch)
__device__ float g_q[NROWS*DOUT];
__device__ float g_k[NROWS*DOUT];
__device__ float g_v[NROWS*DOUT];
__device__ float g_pacc[(size_t)NPART*128*DOUT];
__device__ float g_pl[NPART*128];
// Pre-split weights (fp16): [mat][n][k], k-contiguous
__device__ __half g_wt[3*64*1024];
// Pre-converted KV tiles (fp16): [b*64+kt][plane][4608]
//   plane 0 = K [key][d], 1 = Vt [d][key]
__device__ __half g_tiles[(size_t)BB*64*2*PLANE_ELEMS];

// ---------------------------------------------------------------------------
// fp16 helpers: cvtf2 packs first arg into LOW 16 bits (even element)
// ---------------------------------------------------------------------------
__device__ __forceinline__ uint32_t cvtf2(float lo, float hi) {
    uint32_t r;
    asm("cvt.rn.f16x2.f32 %0, %1, %2;" : "=r"(r) : "f"(hi), "f"(lo));
    return r;
}

__device__ __forceinline__ uint32_t smem_u32(const void* p) {
    uint32_t a;
    asm("{ .reg .u64 t; cvta.to.shared.u64 t, %1; cvt.u32.u64 %0, t; }"
        : "=r"(a) : "l"(p));
    return a;
}

// mma.sync m16n8k16 row.col f16 -> f32 (sm_80+ PTX; frag layout validated r5-13)
__device__ __forceinline__ void mma_f16(float* d, uint32_t a0, uint32_t a1,
                                        uint32_t a2, uint32_t a3,
                                        uint32_t b0, uint32_t b1) {
    asm("mma.sync.aligned.m16n8k16.row.col.f32.f16.f16.f32 "
        "{%0,%1,%2,%3}, {%4,%5,%6,%7}, {%8,%9}, {%0,%1,%2,%3};"
        : "+f"(d[0]), "+f"(d[1]), "+f"(d[2]), "+f"(d[3])
        : "r"(a0), "r"(a1), "r"(a2), "r"(a3), "r"(b0), "r"(b1));
}

// ldmatrix m8n8.x4 (validated r9-r13)
__device__ __forceinline__ void ldm_x4(uint32_t& r0, uint32_t& r1,
                                       uint32_t& r2, uint32_t& r3, uint32_t addr) {
    asm volatile("ldmatrix.sync.aligned.m8n8.x4.shared.b16 {%0,%1,%2,%3}, [%4];"
                 : "=r"(r0), "=r"(r1), "=r"(r2), "=r"(r3) : "r"(addr));
}

// ---------------------------------------------------------------------------
// Kernel 0: convert W to fp16, transposed to [mat][n][k] (k-contiguous)
// ---------------------------------------------------------------------------
__global__ __launch_bounds__(256) void prep_w_kernel(
    const float* __restrict__ Wq, const float* __restrict__ Wk,
    const float* __restrict__ Wv)
{
    int idx = blockIdx.x * 256 + threadIdx.x;     // 0 .. 196607
    int mat = idx >> 16;
    int r   = idx & 65535;
    const float* W = (mat == 0) ? Wq : (mat == 1) ? Wk : Wv;
    float w = W[r];                                // coalesced read: r = k*64+n
    int k = r >> 6;
    int n = r & 63;
    g_wt[(mat << 16) + n * 1024 + k] = __float2half(w);
}

// ---------------------------------------------------------------------------
// Kernel 1: QKV via mma.sync fp16 single-pass, fp32 accumulate.
// grid (3, 256): mat = blockIdx.x (FASTEST-varying) so the three blocks
// reading the same x rows are raster-adjacent -> co-resident -> x served
// from L2 for mats 1,2 (DRAM x traffic 192MB -> 64MB).
// ---------------------------------------------------------------------------
#define QWTS 40   // f16 elements per smem B row (80B stride)
#define QBUF (64*QWTS)   // 2560 halves = 5120 B per buffer

__global__ __launch_bounds__(128) void qkv_mma_kernel(
    const float* __restrict__ x,
    const float* __restrict__ bq, const float* __restrict__ bk,
    const float* __restrict__ bv)
{
    __shared__ __align__(16) __half bs[2 * QBUF];   // 10240 B

    int tid  = threadIdx.x;
    int wid  = tid >> 5;
    int lane = tid & 31;
    int g    = lane >> 2;     // 0..7
    int t    = lane & 3;      // 0..3
    int mat  = blockIdx.x;
    int r0   = blockIdx.y * 64;
    int rA   = r0 + wid * 16 + g;          // rows rA and rA+8

    const __half* wsrc = &g_wt[mat << 16];
    float* out = (mat == 0) ? g_q : (mat == 1) ? g_k : g_v;
    const float* bias = (mat == 0) ? bq : (mat == 1) ? bk : bv;

    uint32_t bbase = smem_u32(bs);
    uint32_t laneoff = (((lane >> 4) * 8 + (lane & 7)) * QWTS) * 2
                       + (((lane >> 3) & 1) * 8) * 2;

    float acc[8][4];
#pragma unroll
    for (int nt = 0; nt < 8; nt++)
#pragma unroll
        for (int i = 0; i < 4; i++) acc[nt][i] = 0.f;

    const float* xlo = &x[(size_t)rA * DIN];
    const float* xhi = &x[(size_t)(rA + 8) * DIN];

    // prologue: stage chunk 0 into buffer 0 (256 uint4 = 4096B of W data)
#pragma unroll
    for (int i = tid; i < 256; i += 128) {
        int row = i >> 2;
        int cc  = i & 3;
        asm volatile("cp.async.cg.shared.global [%0], [%1], 16;"
                     :: "r"(bbase + (row * QWTS + cc * 8) * 2),
                        "l"((const char*)&wsrc[row * 1024 + cc * 8])
                     : "memory");
    }
    asm volatile("cp.async.commit_group;" ::: "memory");

    int ib = 0;
    for (int c = 0; c < 32; c++, ib ^= 1) {
        if (c + 1 < 32) {
            int c0n = (c + 1) * 32;
            uint32_t nb = bbase + (ib ^ 1) * QBUF * 2;
#pragma unroll
            for (int i = tid; i < 256; i += 128) {
                int row = i >> 2;
                int cc  = i & 3;
                asm volatile("cp.async.cg.shared.global [%0], [%1], 16;"
                             :: "r"(nb + (row * QWTS + cc * 8) * 2),
                                "l"((const char*)&wsrc[row * 1024 + c0n + cc * 8])
                             : "memory");
            }
            asm volatile("cp.async.commit_group;" ::: "memory");
            asm volatile("cp.async.wait_group 1;" ::: "memory");
        } else {
            asm volatile("cp.async.wait_group 0;" ::: "memory");
        }
        __syncthreads();

        uint32_t bufb = bbase + ib * QBUF * 2;
        int c0 = c * 32;
#pragma unroll
        for (int ks = 0; ks < 2; ks++) {
            int kk = c0 + ks * 16;
            float2 xa = *(const float2*)&xlo[kk + 2 * t];
            float2 xb = *(const float2*)&xlo[kk + 2 * t + 8];
            float2 xc = *(const float2*)&xhi[kk + 2 * t];
            float2 xd = *(const float2*)&xhi[kk + 2 * t + 8];
            uint32_t a0 = cvtf2(xa.x, xa.y);
            uint32_t a1 = cvtf2(xc.x, xc.y);
            uint32_t a2 = cvtf2(xb.x, xb.y);
            uint32_t a3 = cvtf2(xd.x, xd.y);

#pragma unroll
            for (int np = 0; np < 4; np++) {     // nt pair 2np, 2np+1
                uint32_t off = (np * 16 * QWTS + ks * 16) * 2;
                uint32_t b0a, b1a, b0b, b1b;
                ldm_x4(b0a, b1a, b0b, b1b, bufb + off + laneoff);
                mma_f16(acc[2*np],   a0, a1, a2, a3, b0a, b1a);
                mma_f16(acc[2*np+1], a0, a1, a2, a3, b0b, b1b);
            }
        }
        __syncthreads();
    }

#pragma unroll
    for (int nt = 0; nt < 8; nt++) {
        int col = nt * 8 + 2 * t;
        float b0 = bias[col], b1 = bias[col + 1];
        float2 o0 = make_float2(acc[nt][0] + b0, acc[nt][1] + b1);
        float2 o1 = make_float2(acc[nt][2] + b0, acc[nt][3] + b1);
        *(float2*)&out[(size_t)rA * DOUT + col] = o0;
        *(float2*)&out[(size_t)(rA + 8) * DOUT + col] = o1;
    }
}

// ---------------------------------------------------------------------------
// Kernel 1b: pre-convert K/V into fp16 tile images (2 planes: K, Vt)
// ---------------------------------------------------------------------------
__global__ __launch_bounds__(256) void preconv_kernel()
{
    __shared__ float vsm[64 * 65];

    int bt  = blockIdx.x;             // b*64 + kt
    int b   = bt >> 6;
    int kt  = bt & 63;
    int tid = threadIdx.x;

    __half* tk = &g_tiles[(size_t)bt * 2 * PLANE_ELEMS];
    __half* tv = tk + PLANE_ELEMS;

#pragma unroll
    for (int p = 0; p < 4; p++) {
        int idx4 = tid + p * 256;            // 0..1023 float4s
        int key  = idx4 >> 4;
        int dq   = (idx4 & 15) * 4;
        size_t gsrc = ((size_t)b * SS + kt * 64 + key) * DOUT + dq;

        float4 kv = *(const float4*)&g_k[gsrc];
        uint32_t h0 = cvtf2(kv.x, kv.y), h1 = cvtf2(kv.z, kv.w);
        *(uint2*)&tk[key * KST + dq] = make_uint2(h0, h1);

        float4 vv = *(const float4*)&g_v[gsrc];
        vsm[key * 65 + dq + 0] = vv.x;
        vsm[key * 65 + dq + 1] = vv.y;
        vsm[key * 65 + dq + 2] = vv.z;
        vsm[key * 65 + dq + 3] = vv.w;
    }
    __syncthreads();

    {
        int d  = tid >> 2;
        int kq = (tid & 3) * 16;
        uint32_t h[8];
#pragma unroll
        for (int i = 0; i < 8; i++) {
            h[i] = cvtf2(vsm[(kq + 2 * i) * 65 + d],
                         vsm[(kq + 2 * i + 1) * 65 + d]);
        }
        uint4* dst = (uint4*)&tv[d * KST + kq];
        dst[0] = make_uint4(h[0], h[1], h[2], h[3]);
        dst[1] = make_uint4(h[4], h[5], h[6], h[7]);
    }
}

// ---------------------------------------------------------------------------
// Kernel 2: flash-attention partial, fp16 single-pass.
// Round-14: warp-uniform fast path for fully-unmasked tiles (skips the 32
// per-element causal compares on all but diagonal tiles).
// ---------------------------------------------------------------------------
__global__ __launch_bounds__(256, 2) void attn_mma_kernel()
{
    extern __shared__ __align__(16) char smdyn[];

    int blk = blockIdx.x;
    int b   = blk / (NQT * MAXCH);
    int rem = blk % (NQT * MAXCH);
    int qt  = rem / MAXCH;
    int ch  = rem % MAXCH;
    int nch = (qt >> 2) + 1;   // ceil((qt+1)*128 / 512)
    if (ch >= nch) return;

    int tid  = threadIdx.x;
    int w    = tid >> 5;
    int lane = tid & 31;
    int g    = lane >> 2;
    int t    = lane & 3;

    int rg  = qt * 128 + w * 16 + g;   // query rows rg and rg+8
    int rg8 = rg + 8;
    int rwmin = qt * 128 + w * 16;     // min row in this warp's tile

    uint32_t smT_base = smem_u32(smdyn);
    uint32_t laneoff = ((((lane >> 4) * 8 + (lane & 7)) * KST
                         + ((lane >> 3) & 1) * 8) * 2);

    // Q fragments (scale folded in), fp16
    const float SCALE = 0.015625f;   // 1/sqrt(4096)
    uint32_t qh[4][4];
    {
        const float* q0 = &g_q[((size_t)b * SS + rg) * DOUT];
        const float* q8 = &g_q[((size_t)b * SS + rg8) * DOUT];
#pragma unroll
        for (int ks = 0; ks < 4; ks++) {
            float2 xa = *(const float2*)&q0[ks * 16 + 2 * t];
            float2 xc = *(const float2*)&q8[ks * 16 + 2 * t];
            float2 xb = *(const float2*)&q0[ks * 16 + 2 * t + 8];
            float2 xd = *(const float2*)&q8[ks * 16 + 2 * t + 8];
            qh[ks][0] = cvtf2(xa.x * SCALE, xa.y * SCALE);
            qh[ks][1] = cvtf2(xc.x * SCALE, xc.y * SCALE);
            qh[ks][2] = cvtf2(xb.x * SCALE, xb.y * SCALE);
            qh[ks][3] = cvtf2(xd.x * SCALE, xd.y * SCALE);
        }
    }

    float o[8][4];
#pragma unroll
    for (int nd = 0; nd < 8; nd++)
#pragma unroll
        for (int i = 0; i < 4; i++) o[nd][i] = 0.f;
    float lg = 0.f, lg8 = 0.f;

    int k0 = ch * CHUNK;
    int k1 = min(k0 + CHUNK, (qt + 1) * 128);

    // ---- prologue: stage first tile (1152 uint4 = 18432B) into buffer 0
    {
        const char* src =
            (const char*)&g_tiles[(size_t)(b * 64 + (k0 >> 6)) * 2 * PLANE_ELEMS];
        for (int i = tid; i < 1152; i += 256) {
            asm volatile("cp.async.cg.shared.global [%0], [%1], 16;"
                         :: "r"(smT_base + i * 16), "l"(src + (size_t)i * 16)
                         : "memory");
        }
        asm volatile("cp.async.commit_group;" ::: "memory");
    }

    int ib = 0;
    for (int kt = k0; kt < k1; kt += 64, ib ^= 1) {
        int ktn = kt + 64;
        if (ktn < k1) {
            uint32_t nb = smT_base + (ib ^ 1) * TILE2_BYTES;
            const char* src =
                (const char*)&g_tiles[(size_t)(b * 64 + (ktn >> 6)) * 2 * PLANE_ELEMS];
            for (int i = tid; i < 1152; i += 256) {
                asm volatile("cp.async.cg.shared.global [%0], [%1], 16;"
                             :: "r"(nb + i * 16), "l"(src + (size_t)i * 16)
                             : "memory");
            }
            asm volatile("cp.async.commit_group;" ::: "memory");
            asm volatile("cp.async.wait_group 1;" ::: "memory");
        } else {
            asm volatile("cp.async.wait_group 0;" ::: "memory");
        }
        __syncthreads();

        uint32_t bufb = smT_base + ib * TILE2_BYTES;
        uint32_t aK = bufb + laneoff;
        uint32_t aV = bufb + PLANE_ELEMS * 2 + laneoff;

        // ---- QK^T: single-pass fp16, fp32 C
        float c[8][4];
#pragma unroll
        for (int nc = 0; nc < 8; nc++)
#pragma unroll
            for (int i = 0; i < 4; i++) c[nc][i] = 0.f;

#pragma unroll
        for (int ks = 0; ks < 4; ks++) {
#pragma unroll
            for (int np = 0; np < 4; np++) {     // nc pair 2np, 2np+1
                uint32_t off = (np * 16 * KST + ks * 16) * 2;
                uint32_t b0a, b1a, b0b, b1b;
                ldm_x4(b0a, b1a, b0b, b1b, aK + off);
                mma_f16(c[2*np],   qh[ks][0], qh[ks][1], qh[ks][2], qh[ks][3], b0a, b1a);
                mma_f16(c[2*np+1], qh[ks][0], qh[ks][1], qh[ks][2], qh[ks][3], b0b, b1b);
            }
        }

        // ---- exp (+ causal mask only on diagonal tiles); pack P fragments
        uint32_t pah[4][4];
        if (kt + 63 <= rwmin) {
            // fully unmasked tile (warp-uniform branch)
#pragma unroll
            for (int nc = 0; nc < 8; nc++) {
                float e0 = __expf(c[nc][0]);
                float e1 = __expf(c[nc][1]);
                float e2 = __expf(c[nc][2]);
                float e3 = __expf(c[nc][3]);
                lg  += e0 + e1;
                lg8 += e2 + e3;
                uint32_t h01 = cvtf2(e0, e1), h23 = cvtf2(e2, e3);
                int j = nc >> 1;
                if ((nc & 1) == 0) { pah[j][0] = h01; pah[j][1] = h23; }
                else               { pah[j][2] = h01; pah[j][3] = h23; }
            }
        } else {
#pragma unroll
            for (int nc = 0; nc < 8; nc++) {
                int col0 = kt + nc * 8 + 2 * t;
                int col1 = col0 + 1;
                float e0 = (col0 <= rg)  ? __expf(c[nc][0]) : 0.f;
                float e1 = (col1 <= rg)  ? __expf(c[nc][1]) : 0.f;
                float e2 = (col0 <= rg8) ? __expf(c[nc][2]) : 0.f;
                float e3 = (col1 <= rg8) ? __expf(c[nc][3]) : 0.f;
                lg  += e0 + e1;
                lg8 += e2 + e3;
                uint32_t h01 = cvtf2(e0, e1), h23 = cvtf2(e2, e3);
                int j = nc >> 1;
                if ((nc & 1) == 0) { pah[j][0] = h01; pah[j][1] = h23; }
                else               { pah[j][2] = h01; pah[j][3] = h23; }
            }
        }

        // ---- PV: single-pass fp16
#pragma unroll
        for (int j = 0; j < 4; j++) {
#pragma unroll
            for (int np = 0; np < 4; np++) {     // nd pair 2np, 2np+1
                uint32_t off = (np * 16 * KST + j * 16) * 2;
                uint32_t b0a, b1a, b0b, b1b;
                ldm_x4(b0a, b1a, b0b, b1b, aV + off);
                mma_f16(o[2*np],   pah[j][0], pah[j][1], pah[j][2], pah[j][3], b0a, b1a);
                mma_f16(o[2*np+1], pah[j][0], pah[j][1], pah[j][2], pah[j][3], b0b, b1b);
            }
        }
        __syncthreads();   // reads of buf ib done before next prefetch overwrites
    }

    // ---- l reduce across the t-quad (lanes g*4 + t)
    lg  += __shfl_xor_sync(0xffffffffu, lg, 1);
    lg  += __shfl_xor_sync(0xffffffffu, lg, 2);
    lg8 += __shfl_xor_sync(0xffffffffu, lg8, 1);
    lg8 += __shfl_xor_sync(0xffffffffu, lg8, 2);

    int pidx = (b * NQT + qt) * MAXCH + ch;
    int rl = w * 16 + g;
    if (t == 0) {
        g_pl[pidx * 128 + rl]     = lg;
        g_pl[pidx * 128 + rl + 8] = lg8;
    }
    float* pa0 = &g_pacc[((size_t)pidx * 128 + rl) * DOUT];
    float* pa8 = &g_pacc[((size_t)pidx * 128 + rl + 8) * DOUT];
#pragma unroll
    for (int nd = 0; nd < 8; nd++) {
        *(float2*)&pa0[nd * 8 + 2 * t] = make_float2(o[nd][0], o[nd][1]);
        *(float2*)&pa8[nd * 8 + 2 * t] = make_float2(o[nd][2], o[nd][3]);
    }
}

// ---------------------------------------------------------------------------
// Kernel 3: combine split-KV partials. 256 threads = 4 rows x 64 dims.
// ---------------------------------------------------------------------------
__global__ __launch_bounds__(256) void combine_kernel(float* __restrict__ out)
{
    int rowg = blockIdx.x * 4 + (threadIdx.x >> 6);
    int b    = rowg / SS;
    int row  = rowg % SS;
    int qt   = row >> 7;
    int r    = row & 127;
    int nch  = (qt >> 2) + 1;
    int d    = threadIdx.x & 63;
    int pbase = (b * NQT + qt) * MAXCH;

    float L = 0.f, o = 0.f;
    for (int c = 0; c < nch; c++) {
        L += g_pl[(pbase + c) * 128 + r];
        o += g_pacc[((size_t)(pbase + c) * 128 + r) * DOUT + d];
    }
    out[((size_t)b * SS + row) * DOUT + d] = o / L;
}

// ---------------------------------------------------------------------------
extern "C" void kernel_launch(void* const* d_in, const int* in_sizes, int n_in,
                              void* d_out, int out_size)
{
    const float* x  = (const float*)d_in[0];
    const float* Wq = (const float*)d_in[1];
    const float* bq = (const float*)d_in[2];
    const float* Wk = (const float*)d_in[3];
    const float* bk = (const float*)d_in[4];
    const float* Wv = (const float*)d_in[5];
    const float* bv = (const float*)d_in[6];
    float* out = (float*)d_out;

    cudaFuncSetAttribute(attn_mma_kernel,
                         cudaFuncAttributeMaxDynamicSharedMemorySize,
                         2 * TILE2_BYTES);

    prep_w_kernel<<<768, 256>>>(Wq, Wk, Wv);
    dim3 gq(3, NROWS / 64);   // mat fastest-varying -> x L2 reuse
    qkv_mma_kernel<<<gq, 128>>>(x, bq, bk, bv);
    preconv_kernel<<<BB * 64, 256>>>();
    attn_mma_kernel<<<NPART, 256, 2 * TILE2_BYTES>>>();
    combine_kernel<<<BB * SS / 4, 256>>>(out);
}